// round 12
// baseline (speedup 1.0000x reference)
#include <cuda_runtime.h>
#include <cuda_bf16.h>
#include <math.h>
#include <cstdint>

// ---------------- problem constants ----------------
#define NN 100000
#define NC 50000
#define EE 400000
#define ND 43
#define CD 2
#define HID 128
#define NL 4
#define SLOPE 0.2f
#define LNEPS 1e-5f

#define SCHUNK 2048
#define NB_M ((NC + SCHUNK - 1) / SCHUNK)   // 25
#define NB_C ((NN + SCHUNK - 1) / SCHUNK)   // 49
#define NB_T (NB_M + NB_C)                  // 74

// padded K stride for smem tiles (conflict-free ldmatrix rows)
#define PK 136
#define W_BYTES (128 * PK * 2)              // 34816 per W tile (hi or lo)
#define X_BYTES (64 * PK * 2)               // 17408 per X tile (hi or lo)
#define MM_SMEM (2 * W_BYTES + 2 * X_BYTES) // 104448 -> 2 blocks/SM
#define XH_OFF (2 * W_BYTES)
#define XL_OFF (2 * W_BYTES + X_BYTES)
#define WL_OFF (W_BYTES)
#define GRIDP 296                            // 2 blocks/SM x 148 SMs

// ---------------- device scratch (static, no allocation) ----------------
__device__ float g_xn[(size_t)NN * HID];
__device__ float g_xc[(size_t)NC * HID];
__device__ float g_xl[(size_t)NN * HID];    // n2c wl output (NN rows)
__device__ float g_xr[(size_t)NC * HID];    // n2c wr output (NC rows)
__device__ float g_xl2[(size_t)NC * HID];   // c2n wl output (NC rows)
__device__ float g_xr2[(size_t)NN * HID];   // c2n wr output (NN rows)
__device__ int g_deg_m[NC];
__device__ int g_cur_m[NC];
__device__ int g_deg_c[NN];
__device__ int g_cur_c[NN];
__device__ int g_off_m[NC + 1];
__device__ int g_off_c[NN + 1];
__device__ int g_src_m[EE];
__device__ int g_src_c[EE];
__device__ int g_part[128];
// transposed+split weights: 16 matrices [n][k] bf16 (idx = group*4 + layer)
__device__ __nv_bfloat16 g_wth[16 * HID * HID];
__device__ __nv_bfloat16 g_wtl[16 * HID * HID];

// ---------------- helpers ----------------
__device__ __forceinline__ void mma16816(float* d, const uint32_t* a, const uint32_t* b) {
    asm volatile(
        "mma.sync.aligned.m16n8k16.row.col.f32.bf16.bf16.f32 "
        "{%0,%1,%2,%3}, {%4,%5,%6,%7}, {%8,%9}, {%0,%1,%2,%3};"
        : "+f"(d[0]), "+f"(d[1]), "+f"(d[2]), "+f"(d[3])
        : "r"(a[0]), "r"(a[1]), "r"(a[2]), "r"(a[3]), "r"(b[0]), "r"(b[1]));
}
__device__ __forceinline__ void ldsm_x4(uint32_t* r, uint32_t addr) {
    asm volatile("ldmatrix.sync.aligned.m8n8.x4.shared.b16 {%0,%1,%2,%3}, [%4];"
                 : "=r"(r[0]), "=r"(r[1]), "=r"(r[2]), "=r"(r[3])
                 : "r"(addr));
}
__device__ __forceinline__ uint32_t smem_u32(const void* p) {
    uint32_t a;
    asm("{ .reg .u64 t; cvta.to.shared.u64 t, %1; cvt.u32.u64 %0, t; }" : "=r"(a) : "l"(p));
    return a;
}
__device__ __forceinline__ void split4(float4 x, uint2& hi, uint2& lo) {
    __nv_bfloat162 h01 = __floats2bfloat162_rn(x.x, x.y);
    __nv_bfloat162 h23 = __floats2bfloat162_rn(x.z, x.w);
    float r0 = x.x - __low2float(h01);
    float r1 = x.y - __high2float(h01);
    float r2 = x.z - __low2float(h23);
    float r3 = x.w - __high2float(h23);
    __nv_bfloat162 l01 = __floats2bfloat162_rn(r0, r1);
    __nv_bfloat162 l23 = __floats2bfloat162_rn(r2, r3);
    hi.x = *reinterpret_cast<uint32_t*>(&h01);
    hi.y = *reinterpret_cast<uint32_t*>(&h23);
    lo.x = *reinterpret_cast<uint32_t*>(&l01);
    lo.y = *reinterpret_cast<uint32_t*>(&l23);
}

// ---------------- weight prep: transpose + bf16 split (16 matrices) ----------------
__global__ void prep_weights_kernel(const float* __restrict__ n2c_wl,
                                    const float* __restrict__ n2c_wr,
                                    const float* __restrict__ c2n_wl,
                                    const float* __restrict__ c2n_wr,
                                    __nv_bfloat16* __restrict__ wth,
                                    __nv_bfloat16* __restrict__ wtl) {
    int idx = blockIdx.x;  // 0..15
    int grp = idx >> 2, lay = idx & 3;
    const float* W = (grp == 0) ? n2c_wl : (grp == 1) ? n2c_wr : (grp == 2) ? c2n_wl : c2n_wr;
    W += (size_t)lay * HID * HID;
    __nv_bfloat16* oh = wth + (size_t)idx * HID * HID;
    __nv_bfloat16* ol = wtl + (size_t)idx * HID * HID;
    for (int e = threadIdx.x; e < HID * HID; e += blockDim.x) {
        int k = e >> 7, n = e & 127;
        float w = W[e];  // W[k][n]
        __nv_bfloat16 h = __float2bfloat16_rn(w);
        float r = w - __bfloat162float(h);
        oh[n * HID + k] = h;
        ol[n * HID + k] = __float2bfloat16_rn(r);
    }
}

// ---------------- persistent HMMA GEMM: Y[N,128] = X[N,128] @ W + b ------------------
__global__ void __launch_bounds__(256, 2)
mm_gemm_p(const float* __restrict__ X, const __nv_bfloat16* __restrict__ Gh,
          const __nv_bfloat16* __restrict__ Gl, const float* __restrict__ bias,
          float* __restrict__ Y, int N) {
    extern __shared__ char smem[];
    __nv_bfloat16* Wh = (__nv_bfloat16*)(smem);
    __nv_bfloat16* Wl = (__nv_bfloat16*)(smem + WL_OFF);
    __nv_bfloat16* Xh = (__nv_bfloat16*)(smem + XH_OFF);
    __nv_bfloat16* Xl = (__nv_bfloat16*)(smem + XL_OFF);

    int tid = threadIdx.x;
    int lane = tid & 31;
    int wid = tid >> 5;
    uint32_t sbase = smem_u32(smem);

#pragma unroll
    for (int it = 0; it < 8; it++) {
        int n = it * 16 + (tid >> 4);
        int kc = (tid & 15) * 8;
        uint4 vh = *reinterpret_cast<const uint4*>(Gh + n * HID + kc);
        uint4 vl = *reinterpret_cast<const uint4*>(Gl + n * HID + kc);
        *reinterpret_cast<uint4*>(&Wh[n * PK + kc]) = vh;
        *reinterpret_cast<uint4*>(&Wl[n * PK + kc]) = vl;
    }

    int row0 = (wid & 1) * 32;
    int col0 = (wid >> 1) * 32;
    int gr4 = lane >> 2;
    int l2 = (lane & 3) * 2;

    uint32_t aoff = (uint32_t)(((row0 + (lane & 15)) * PK + ((lane >> 4) & 1) * 8) * 2);
    uint32_t boff = (uint32_t)(((col0 + (lane & 7) + ((lane >> 4) & 1) * 8) * PK +
                                ((lane >> 3) & 1) * 8) * 2);

    int ntiles = (N + 63) >> 6;
#pragma unroll 1
    for (int t = blockIdx.x; t < ntiles; t += gridDim.x) {
        int rb = t * 64;
        __syncthreads();
#pragma unroll
        for (int it = 0; it < 8; it++) {
            int r = it * 8 + (tid >> 5);
            int gr = rb + r;
            int kc = (tid & 31) * 4;
            float4 x = (gr < N) ? *reinterpret_cast<const float4*>(X + (size_t)gr * HID + kc)
                                : make_float4(0.f, 0.f, 0.f, 0.f);
            uint2 hi, lo;
            split4(x, hi, lo);
            *reinterpret_cast<uint2*>(&Xh[r * PK + kc]) = hi;
            *reinterpret_cast<uint2*>(&Xl[r * PK + kc]) = lo;
        }
        __syncthreads();

        float acc[2][4][4];
#pragma unroll
        for (int mt = 0; mt < 2; mt++)
#pragma unroll
            for (int nt = 0; nt < 4; nt++)
#pragma unroll
                for (int j = 0; j < 4; j++) acc[mt][nt][j] = 0.f;

#pragma unroll
        for (int ks = 0; ks < 8; ks++) {
            uint32_t kb = ks * 32;
            uint32_t ah[2][4], al[2][4], bh[4][2], bl[4][2];
            uint32_t aXh = sbase + XH_OFF + aoff + kb;
            uint32_t aXl = sbase + XL_OFF + aoff + kb;
            ldsm_x4(ah[0], aXh);
            ldsm_x4(ah[1], aXh + 16 * PK * 2);
            ldsm_x4(al[0], aXl);
            ldsm_x4(al[1], aXl + 16 * PK * 2);
            uint32_t bWh = sbase + boff + kb;
            uint32_t bWl = sbase + WL_OFF + boff + kb;
            ldsm_x4(&bh[0][0], bWh);
            ldsm_x4(&bh[2][0], bWh + 16 * PK * 2);
            ldsm_x4(&bl[0][0], bWl);
            ldsm_x4(&bl[2][0], bWl + 16 * PK * 2);
#pragma unroll
            for (int mt = 0; mt < 2; mt++)
#pragma unroll
                for (int nt = 0; nt < 4; nt++) {
                    mma16816(acc[mt][nt], ah[mt], bh[nt]);
                    mma16816(acc[mt][nt], ah[mt], bl[nt]);
                    mma16816(acc[mt][nt], al[mt], bh[nt]);
                }
        }

#pragma unroll
        for (int nt = 0; nt < 4; nt++) {
            int c = col0 + nt * 8 + l2;
            float bx = bias[c], by = bias[c + 1];
#pragma unroll
            for (int mt = 0; mt < 2; mt++) {
                int r0 = rb + row0 + mt * 16 + gr4;
                if (r0 < N) {
                    float2 v = make_float2(acc[mt][nt][0] + bx, acc[mt][nt][1] + by);
                    *reinterpret_cast<float2*>(Y + (size_t)r0 * HID + c) = v;
                }
                if (r0 + 8 < N) {
                    float2 v = make_float2(acc[mt][nt][2] + bx, acc[mt][nt][3] + by);
                    *reinterpret_cast<float2*>(Y + (size_t)(r0 + 8) * HID + c) = v;
                }
            }
        }
    }
}

// ---------------- merged input projection ----------------
__global__ void proj_both_kernel(const float* __restrict__ Xn, const float* __restrict__ Wn,
                                 const float* __restrict__ bn, float* __restrict__ Yn,
                                 const float* __restrict__ Xc, const float* __restrict__ Wc,
                                 const float* __restrict__ bc, float* __restrict__ Yc) {
    __shared__ float xs[64];
    int blk = blockIdx.x;
    int n = threadIdx.x;  // 128 threads
    const float* X;
    const float* W;
    const float* b;
    float* Y;
    int row, K;
    if (blk < NN) {
        X = Xn; W = Wn; b = bn; Y = Yn; row = blk; K = ND;
    } else {
        X = Xc; W = Wc; b = bc; Y = Yc; row = blk - NN; K = CD;
    }
    if (n < K) xs[n] = X[(size_t)row * K + n];
    __syncthreads();
    float acc = b[n];
    for (int k = 0; k < K; k++) acc = fmaf(xs[k], W[k * HID + n], acc);
    Y[(size_t)row * HID + n] = acc;
}

// ---------------- CSR build ----------------
__global__ void build_zero_kernel(int* __restrict__ dm, int* __restrict__ dc) {
    int i = blockIdx.x * blockDim.x + threadIdx.x;
    if (i < NC) dm[i] = 0;
    if (i < NN) dc[i] = 0;
}
__global__ void build_hist_kernel(const int* __restrict__ mdst, const int* __restrict__ cdst,
                                  int* __restrict__ dm, int* __restrict__ dc, int E) {
    int i = blockIdx.x * blockDim.x + threadIdx.x;
    if (i < E)
        atomicAdd(&dm[mdst[i]], 1);
    else if (i < 2 * E)
        atomicAdd(&dc[cdst[i - E]], 1);
}
__global__ void scanA_kernel(const int* __restrict__ dm, const int* __restrict__ dc,
                             int* __restrict__ part) {
    int b = blockIdx.x;
    const int* deg;
    int n, c0;
    if (b < NB_M) { deg = dm; n = NC; c0 = b * SCHUNK; }
    else          { deg = dc; n = NN; c0 = (b - NB_M) * SCHUNK; }
    int t = threadIdx.x;
    int base = c0 + t * 8;
    int s = 0;
#pragma unroll
    for (int i = 0; i < 8; i++) {
        int idx = base + i;
        if (idx < n) s += deg[idx];
    }
#pragma unroll
    for (int o = 16; o > 0; o >>= 1) s += __shfl_xor_sync(0xffffffffu, s, o);
    __shared__ int red[8];
    if ((t & 31) == 0) red[t >> 5] = s;
    __syncthreads();
    if (t == 0) {
        int tot = 0;
#pragma unroll
        for (int i = 0; i < 8; i++) tot += red[i];
        part[b] = tot;
    }
}
__global__ void scanB_kernel(int* __restrict__ part, int* __restrict__ om,
                             int* __restrict__ oc, int E) {
    __shared__ int sm_[128];
    int t = threadIdx.x;  // 128
    sm_[t] = (t < NB_T) ? part[t] : 0;
    __syncthreads();
    if (t == 0) {
        int run = 0;
        for (int i = 0; i < NB_M; i++) { int x = sm_[i]; sm_[i] = run; run += x; }
        run = 0;
        for (int i = NB_M; i < NB_T; i++) { int x = sm_[i]; sm_[i] = run; run += x; }
        om[NC] = E;
        oc[NN] = E;
    }
    __syncthreads();
    if (t < NB_T) part[t] = sm_[t];
}
__global__ void scanC_kernel(const int* __restrict__ dm, const int* __restrict__ dc,
                             const int* __restrict__ part, int* __restrict__ om,
                             int* __restrict__ oc, int* __restrict__ cm,
                             int* __restrict__ cc) {
    int b = blockIdx.x;
    const int* deg;
    int *off, *cur;
    int n, c0;
    if (b < NB_M) { deg = dm; off = om; cur = cm; n = NC; c0 = b * SCHUNK; }
    else          { deg = dc; off = oc; cur = cc; n = NN; c0 = (b - NB_M) * SCHUNK; }
    int t = threadIdx.x;  // 256
    int base = c0 + t * 8;
    int v[8];
    int s = 0;
#pragma unroll
    for (int i = 0; i < 8; i++) {
        int idx = base + i;
        v[i] = (idx < n) ? deg[idx] : 0;
        s += v[i];
    }
    int lane = t & 31, w = t >> 5;
    int pre = s;
#pragma unroll
    for (int o = 1; o < 32; o <<= 1) {
        int u = __shfl_up_sync(0xffffffffu, pre, o);
        if (lane >= o) pre += u;
    }
    __shared__ int wsum[8];
    if (lane == 31) wsum[w] = pre;
    __syncthreads();
    if (t == 0) {
        int run = 0;
#pragma unroll
        for (int i = 0; i < 8; i++) { int x = wsum[i]; wsum[i] = run; run += x; }
    }
    __syncthreads();
    int ex = pre - s + wsum[w] + part[b];
#pragma unroll
    for (int i = 0; i < 8; i++) {
        int idx = base + i;
        if (idx < n) {
            off[idx] = ex;
            cur[idx] = ex;
            ex += v[i];
        }
    }
}
__global__ void build_scatter_kernel(const int* __restrict__ msrc, const int* __restrict__ mdst,
                                     const int* __restrict__ csrc_e, const int* __restrict__ cdst,
                                     int* __restrict__ cm, int* __restrict__ cc,
                                     int* __restrict__ sm, int* __restrict__ sc, int E) {
    int i = blockIdx.x * blockDim.x + threadIdx.x;
    if (i < E) {
        int p = atomicAdd(&cm[mdst[i]], 1);
        sm[p] = msrc[i];
    } else if (i < 2 * E) {
        int j = i - E;
        int p = atomicAdd(&cc[cdst[j]], 1);
        sc[p] = csrc_e[j];
    }
}

// ---------------- fused GATv2: 8-edge-chunk online softmax + LN (+optional mean) -----
__device__ __forceinline__ float edge_score(float4 xl4, float4 xr4, float4 at4) {
    float vx = xl4.x + xr4.x; vx = vx > 0.f ? vx : SLOPE * vx;
    float vy = xl4.y + xr4.y; vy = vy > 0.f ? vy : SLOPE * vy;
    float vz = xl4.z + xr4.z; vz = vz > 0.f ? vz : SLOPE * vz;
    float vw = xl4.w + xr4.w; vw = vw > 0.f ? vw : SLOPE * vw;
    float sc = vx * at4.x + vy * at4.y + vz * at4.z + vw * at4.w;
    sc += __shfl_xor_sync(0xffffffffu, sc, 1);
    sc += __shfl_xor_sync(0xffffffffu, sc, 2);
    sc += __shfl_xor_sync(0xffffffffu, sc, 4);
    return sc;
}

// mean_out == nullptr: write LN result to x. Otherwise: skip x store, block-reduce
// o into smem and atomically accumulate column mean into mean_out (scaled 1/n_dst).
// NOTE: grids are exact (n_dst*32 divisible by 256) -> no early-exit warps.
__global__ void gat_kernel(const int* __restrict__ off, const int* __restrict__ csrc,
                           const float* __restrict__ xl, const float* __restrict__ xr,
                           const float* __restrict__ att, const float* __restrict__ bias,
                           const float* __restrict__ lng, const float* __restrict__ lnb,
                           float* __restrict__ x, int n_dst, float* __restrict__ mean_out) {
    __shared__ float blk[128];
    int d = (blockIdx.x * blockDim.x + threadIdx.x) >> 5;
    if (d >= n_dst) return;
    int l = threadIdx.x & 31;
    int ofs = l * 4;
    const float4 z4 = make_float4(0.f, 0.f, 0.f, 0.f);

    float4 xr4 = *(const float4*)(xr + (size_t)d * HID + ofs);
    float4 at4 = *(const float4*)(att + ofs);
    int e0 = off[d], e1 = off[d + 1];

    float m = -1e30f, den = 0.f;
    float4 acc = z4;

    for (int e = e0; e < e1; e += 8) {
        int ns = e1 - e;
        float4 v[8];
        float sc[8];
#pragma unroll
        for (int i = 0; i < 8; i++) {
            if (i < ns) {
                int s = csrc[e + i];
                v[i] = *(const float4*)(xl + (size_t)s * HID + ofs);
            } else {
                v[i] = z4;
            }
        }
#pragma unroll
        for (int i = 0; i < 8; i++) {
            if (i < ns)
                sc[i] = edge_score(v[i], xr4, at4);
            else
                sc[i] = -1e30f;
        }
        float gm = fmaxf(fmaxf(fmaxf(sc[0], sc[1]), fmaxf(sc[2], sc[3])),
                         fmaxf(fmaxf(sc[4], sc[5]), fmaxf(sc[6], sc[7])));
        float nm = fmaxf(m, gm);
        float f = __expf(m - nm);
        float ex[8];
#pragma unroll
        for (int i = 0; i < 8; i++) ex[i] = __expf(sc[i] - nm);
        float ds = ((ex[0] + ex[1]) + (ex[2] + ex[3])) + ((ex[4] + ex[5]) + (ex[6] + ex[7]));
        den = den * f + ds;
        float4 a = z4;
#pragma unroll
        for (int i = 0; i < 8; i++) {
            a.x = fmaf(ex[i], v[i].x, a.x);
            a.y = fmaf(ex[i], v[i].y, a.y);
            a.z = fmaf(ex[i], v[i].z, a.z);
            a.w = fmaf(ex[i], v[i].w, a.w);
        }
        acc.x = acc.x * f + a.x;
        acc.y = acc.y * f + a.y;
        acc.z = acc.z * f + a.z;
        acc.w = acc.w * f + a.w;
        m = nm;
    }

    float inv = (e1 > e0) ? 1.0f / den : 0.0f;
    float4 b4 = *(const float4*)(bias + ofs);
    float4 x4 = *(const float4*)(x + (size_t)d * HID + ofs);
    float4 o;
    o.x = acc.x * inv + b4.x + x4.x;
    o.y = acc.y * inv + b4.y + x4.y;
    o.z = acc.z * inv + b4.z + x4.z;
    o.w = acc.w * inv + b4.w + x4.w;

    float s = o.x + o.y + o.z + o.w;
#pragma unroll
    for (int k = 16; k > 0; k >>= 1) s += __shfl_xor_sync(0xffffffffu, s, k);
    float mu = s * (1.0f / HID);
    float q = (o.x - mu) * (o.x - mu) + (o.y - mu) * (o.y - mu) +
              (o.z - mu) * (o.z - mu) + (o.w - mu) * (o.w - mu);
#pragma unroll
    for (int k = 16; k > 0; k >>= 1) q += __shfl_xor_sync(0xffffffffu, q, k);
    float rs = rsqrtf(q * (1.0f / HID) + LNEPS);
    float4 g4 = *(const float4*)(lng + ofs);
    float4 bb4 = *(const float4*)(lnb + ofs);
    o.x = (o.x - mu) * rs * g4.x + bb4.x;
    o.y = (o.y - mu) * rs * g4.y + bb4.y;
    o.z = (o.z - mu) * rs * g4.z + bb4.z;
    o.w = (o.w - mu) * rs * g4.w + bb4.w;

    if (mean_out == nullptr) {
        *(float4*)(x + (size_t)d * HID + ofs) = o;
    } else {
        if (threadIdx.x < 128) blk[threadIdx.x] = 0.f;
        __syncthreads();
        atomicAdd(&blk[ofs + 0], o.x);
        atomicAdd(&blk[ofs + 1], o.y);
        atomicAdd(&blk[ofs + 2], o.z);
        atomicAdd(&blk[ofs + 3], o.w);
        __syncthreads();
        if (threadIdx.x < 128)
            atomicAdd(&mean_out[threadIdx.x], blk[threadIdx.x] * (1.0f / n_dst));
    }
}

// ---------------- output zero ----------------
__global__ void zero_out_kernel(float* __restrict__ out) { out[threadIdx.x] = 0.0f; }

// ---------------- host orchestration ----------------
static inline int ceil_div(int a, int b) { return (a + b - 1) / b; }

extern "C" void kernel_launch(void* const* d_in, const int* in_sizes, int n_in,
                              void* d_out, int out_size) {
    const float* x_node       = (const float*)d_in[0];
    const float* x_class      = (const float*)d_in[1];
    const int*   member_src   = (const int*)d_in[2];
    const int*   member_dst   = (const int*)d_in[3];
    const int*   contains_src = (const int*)d_in[4];
    const int*   contains_dst = (const int*)d_in[5];
    const float* npw = (const float*)d_in[6];
    const float* npb = (const float*)d_in[7];
    const float* cpw = (const float*)d_in[8];
    const float* cpb = (const float*)d_in[9];
    const float* n2c_wl   = (const float*)d_in[10];
    const float* n2c_bl   = (const float*)d_in[11];
    const float* n2c_wr   = (const float*)d_in[12];
    const float* n2c_br   = (const float*)d_in[13];
    const float* n2c_att  = (const float*)d_in[14];
    const float* n2c_bias = (const float*)d_in[15];
    const float* c2n_wl   = (const float*)d_in[16];
    const float* c2n_bl   = (const float*)d_in[17];
    const float* c2n_wr   = (const float*)d_in[18];
    const float* c2n_br   = (const float*)d_in[19];
    const float* c2n_att  = (const float*)d_in[20];
    const float* c2n_bias = (const float*)d_in[21];
    const float* ln_cg = (const float*)d_in[22];
    const float* ln_cb = (const float*)d_in[23];
    const float* ln_ng = (const float*)d_in[24];
    const float* ln_nb = (const float*)d_in[25];
    float* out = (float*)d_out;

    int E = in_sizes[2];

    float *xn, *xc, *xl, *xr, *xl2, *xr2;
    int *deg_m, *cur_m, *deg_c, *cur_c, *off_m, *off_c, *src_m, *src_c, *part;
    __nv_bfloat16 *wth, *wtl;
    cudaGetSymbolAddress((void**)&xn, g_xn);
    cudaGetSymbolAddress((void**)&xc, g_xc);
    cudaGetSymbolAddress((void**)&xl, g_xl);
    cudaGetSymbolAddress((void**)&xr, g_xr);
    cudaGetSymbolAddress((void**)&xl2, g_xl2);
    cudaGetSymbolAddress((void**)&xr2, g_xr2);
    cudaGetSymbolAddress((void**)&deg_m, g_deg_m);
    cudaGetSymbolAddress((void**)&cur_m, g_cur_m);
    cudaGetSymbolAddress((void**)&deg_c, g_deg_c);
    cudaGetSymbolAddress((void**)&cur_c, g_cur_c);
    cudaGetSymbolAddress((void**)&off_m, g_off_m);
    cudaGetSymbolAddress((void**)&off_c, g_off_c);
    cudaGetSymbolAddress((void**)&src_m, g_src_m);
    cudaGetSymbolAddress((void**)&src_c, g_src_c);
    cudaGetSymbolAddress((void**)&part, g_part);
    cudaGetSymbolAddress((void**)&wth, g_wth);
    cudaGetSymbolAddress((void**)&wtl, g_wtl);

    cudaFuncSetAttribute(mm_gemm_p, cudaFuncAttributeMaxDynamicSharedMemorySize, MM_SMEM);

    // side streams + fork/join events (created once; host-side only)
    static cudaStream_t s1 = nullptr, s2 = nullptr;
    static cudaEvent_t ev[8];
    if (s1 == nullptr) {
        cudaStreamCreateWithFlags(&s1, cudaStreamNonBlocking);
        cudaStreamCreateWithFlags(&s2, cudaStreamNonBlocking);
        for (int i = 0; i < 8; i++) cudaEventCreateWithFlags(&ev[i], cudaEventDisableTiming);
    }

    int g2E = ceil_div(2 * E, 256);
    const size_t WSZ = (size_t)HID * HID;

    // fork CSR build onto s2 immediately (depends only on edge lists)
    cudaEventRecord(ev[6], 0);
    cudaStreamWaitEvent(s2, ev[6], 0);
    build_zero_kernel<<<ceil_div(NN, 256), 256, 0, s2>>>(deg_m, deg_c);
    build_hist_kernel<<<g2E, 256, 0, s2>>>(member_dst, contains_dst, deg_m, deg_c, E);
    scanA_kernel<<<NB_T, 256, 0, s2>>>(deg_m, deg_c, part);
    scanB_kernel<<<1, 128, 0, s2>>>(part, off_m, off_c, E);
    scanC_kernel<<<NB_T, 256, 0, s2>>>(deg_m, deg_c, part, off_m, off_c, cur_m, cur_c);
    build_scatter_kernel<<<g2E, 256, 0, s2>>>(member_src, member_dst, contains_src,
                                              contains_dst, cur_m, cur_c, src_m, src_c, E);
    cudaEventRecord(ev[7], s2);  // CSR done

    // s0: weight prep + input projections
    prep_weights_kernel<<<16, 256>>>(n2c_wl, n2c_wr, c2n_wl, c2n_wr, wth, wtl);
    proj_both_kernel<<<NN + NC, 128>>>(x_node, npw, npb, xn, x_class, cpw, cpb, xc);
    zero_out_kernel<<<1, 128>>>(out);

    // fork: xr = xc @ n2c_wr[0] on s1; xl = xn @ n2c_wl[0] on s0
    cudaEventRecord(ev[0], 0);
    cudaStreamWaitEvent(s1, ev[0], 0);
    mm_gemm_p<<<GRIDP, 256, MM_SMEM, s1>>>(xc, wth + (1 * 4 + 0) * WSZ,
                                           wtl + (1 * 4 + 0) * WSZ, n2c_br, xr, NC);
    cudaEventRecord(ev[1], s1);
    mm_gemm_p<<<GRIDP, 256, MM_SMEM>>>(xn, wth + (0 * 4 + 0) * WSZ,
                                       wtl + (0 * 4 + 0) * WSZ, n2c_bl, xl, NN);
    cudaStreamWaitEvent(0, ev[1], 0);  // join: xr ready
    cudaStreamWaitEvent(0, ev[7], 0);  // join: CSR ready

    for (int l = 0; l < NL; l++) {
        bool last = (l == NL - 1);
        if (!last) {
            // fork: xr2 = xn @ c2n_wr[l] (independent of gat_n2c)
            cudaEventRecord(ev[2], 0);
            cudaStreamWaitEvent(s1, ev[2], 0);
            mm_gemm_p<<<GRIDP, 256, MM_SMEM, s1>>>(xn, wth + (3 * 4 + l) * WSZ,
                                                   wtl + (3 * 4 + l) * WSZ,
                                                   c2n_br + l * HID, xr2, NN);
            cudaEventRecord(ev[3], s1);
        }
        gat_kernel<<<ceil_div(NC * 32, 256), 256>>>(
            off_m, src_m, xl, xr, n2c_att + l * HID, n2c_bias + l * HID,
            ln_cg + l * HID, ln_cb + l * HID, xc, NC, last ? out : nullptr);
        if (last) break;  // layer-3 c2n is dead work (output depends only on xc)

        // fork: xr(next) = xc @ n2c_wr[l+1] (needs updated xc; overlaps gat_c2n)
        cudaEventRecord(ev[4], 0);
        cudaStreamWaitEvent(s1, ev[4], 0);
        mm_gemm_p<<<GRIDP, 256, MM_SMEM, s1>>>(xc, wth + (1 * 4 + (l + 1)) * WSZ,
                                               wtl + (1 * 4 + (l + 1)) * WSZ,
                                               n2c_br + (l + 1) * HID, xr, NC);
        cudaEventRecord(ev[5], s1);

        // s0: xl2 = xc @ c2n_wl[l]
        mm_gemm_p<<<GRIDP, 256, MM_SMEM>>>(xc, wth + (2 * 4 + l) * WSZ,
                                           wtl + (2 * 4 + l) * WSZ,
                                           c2n_bl + l * HID, xl2, NC);
        cudaStreamWaitEvent(0, ev[3], 0);  // join: xr2 ready
        gat_kernel<<<ceil_div(NN * 32, 256), 256>>>(
            off_c, src_c, xl2, xr2, c2n_att + l * HID, c2n_bias + l * HID,
            ln_ng + l * HID, ln_nb + l * HID, xn, NN, nullptr);
        // s0: xl(next) = xn @ n2c_wl[l+1]
        mm_gemm_p<<<GRIDP, 256, MM_SMEM>>>(xn, wth + (0 * 4 + (l + 1)) * WSZ,
                                           wtl + (0 * 4 + (l + 1)) * WSZ,
                                           n2c_bl + (l + 1) * HID, xl, NN);
        cudaStreamWaitEvent(0, ev[5], 0);  // join: xr(next) ready
    }
}

// round 13
// speedup vs baseline: 1.0811x; 1.0811x over previous
#include <cuda_runtime.h>
#include <cuda_bf16.h>
#include <math.h>
#include <cstdint>

// ---------------- problem constants ----------------
#define NN 100000
#define NC 50000
#define EE 400000
#define ND 43
#define CD 2
#define HID 128
#define NL 4
#define SLOPE 0.2f
#define LNEPS 1e-5f

#define SCHUNK 2048
#define NB_M ((NC + SCHUNK - 1) / SCHUNK)   // 25
#define NB_C ((NN + SCHUNK - 1) / SCHUNK)   // 49
#define NB_T (NB_M + NB_C)                  // 74

// padded K stride for smem tiles (conflict-free ldmatrix rows)
#define PK 136
#define W_BYTES (128 * PK * 2)              // 34816 per W tile (hi or lo)
#define X_BYTES (64 * PK * 2)               // 17408 per X tile (hi or lo)
#define MM_SMEM (2 * W_BYTES + 2 * X_BYTES) // 104448 -> 2 blocks/SM
#define XH_OFF (2 * W_BYTES)
#define XL_OFF (2 * W_BYTES + X_BYTES)
#define WL_OFF (W_BYTES)
#define GRIDP 296                            // 2 blocks/SM x 148 SMs

// ---------------- device scratch (static, no allocation) ----------------
__device__ float g_xn[(size_t)NN * HID];
__device__ float g_xc[(size_t)NC * HID];
__device__ float g_xl[(size_t)NN * HID];    // n2c wl output (NN rows)
__device__ float g_xr[(size_t)NC * HID];    // n2c wr output (NC rows)
__device__ float g_xl2[(size_t)NC * HID];   // c2n wl output (NC rows)
__device__ float g_xr2[(size_t)NN * HID];   // c2n wr output (NN rows)
__device__ int g_deg_m[NC];
__device__ int g_cur_m[NC];
__device__ int g_deg_c[NN];
__device__ int g_cur_c[NN];
__device__ int g_off_m[NC + 1];
__device__ int g_off_c[NN + 1];
__device__ int g_src_m[EE];
__device__ int g_src_c[EE];
__device__ int g_part[128];
// transposed+split weights: 16 matrices [n][k] bf16 (idx = group*4 + layer)
__device__ __nv_bfloat16 g_wth[16 * HID * HID];
__device__ __nv_bfloat16 g_wtl[16 * HID * HID];

// ---------------- helpers ----------------
__device__ __forceinline__ void mma16816(float* d, const uint32_t* a, const uint32_t* b) {
    asm volatile(
        "mma.sync.aligned.m16n8k16.row.col.f32.bf16.bf16.f32 "
        "{%0,%1,%2,%3}, {%4,%5,%6,%7}, {%8,%9}, {%0,%1,%2,%3};"
        : "+f"(d[0]), "+f"(d[1]), "+f"(d[2]), "+f"(d[3])
        : "r"(a[0]), "r"(a[1]), "r"(a[2]), "r"(a[3]), "r"(b[0]), "r"(b[1]));
}
__device__ __forceinline__ void ldsm_x4(uint32_t* r, uint32_t addr) {
    asm volatile("ldmatrix.sync.aligned.m8n8.x4.shared.b16 {%0,%1,%2,%3}, [%4];"
                 : "=r"(r[0]), "=r"(r[1]), "=r"(r[2]), "=r"(r[3])
                 : "r"(addr));
}
__device__ __forceinline__ uint32_t smem_u32(const void* p) {
    uint32_t a;
    asm("{ .reg .u64 t; cvta.to.shared.u64 t, %1; cvt.u32.u64 %0, t; }" : "=r"(a) : "l"(p));
    return a;
}
__device__ __forceinline__ void split4(float4 x, uint2& hi, uint2& lo) {
    __nv_bfloat162 h01 = __floats2bfloat162_rn(x.x, x.y);
    __nv_bfloat162 h23 = __floats2bfloat162_rn(x.z, x.w);
    float r0 = x.x - __low2float(h01);
    float r1 = x.y - __high2float(h01);
    float r2 = x.z - __low2float(h23);
    float r3 = x.w - __high2float(h23);
    __nv_bfloat162 l01 = __floats2bfloat162_rn(r0, r1);
    __nv_bfloat162 l23 = __floats2bfloat162_rn(r2, r3);
    hi.x = *reinterpret_cast<uint32_t*>(&h01);
    hi.y = *reinterpret_cast<uint32_t*>(&h23);
    lo.x = *reinterpret_cast<uint32_t*>(&l01);
    lo.y = *reinterpret_cast<uint32_t*>(&l23);
}

// ---------------- weight prep: transpose + bf16 split (16 matrices) ----------------
__global__ void prep_weights_kernel(const float* __restrict__ n2c_wl,
                                    const float* __restrict__ n2c_wr,
                                    const float* __restrict__ c2n_wl,
                                    const float* __restrict__ c2n_wr,
                                    __nv_bfloat16* __restrict__ wth,
                                    __nv_bfloat16* __restrict__ wtl) {
    int idx = blockIdx.x;  // 0..15
    int grp = idx >> 2, lay = idx & 3;
    const float* W = (grp == 0) ? n2c_wl : (grp == 1) ? n2c_wr : (grp == 2) ? c2n_wl : c2n_wr;
    W += (size_t)lay * HID * HID;
    __nv_bfloat16* oh = wth + (size_t)idx * HID * HID;
    __nv_bfloat16* ol = wtl + (size_t)idx * HID * HID;
    for (int e = threadIdx.x; e < HID * HID; e += blockDim.x) {
        int k = e >> 7, n = e & 127;
        float w = W[e];  // W[k][n]
        __nv_bfloat16 h = __float2bfloat16_rn(w);
        float r = w - __bfloat162float(h);
        oh[n * HID + k] = h;
        ol[n * HID + k] = __float2bfloat16_rn(r);
    }
}

// ---------------- persistent HMMA GEMM: Y[N,128] = X[N,128] @ W + b ------------------
__global__ void __launch_bounds__(256, 2)
mm_gemm_p(const float* __restrict__ X, const __nv_bfloat16* __restrict__ Gh,
          const __nv_bfloat16* __restrict__ Gl, const float* __restrict__ bias,
          float* __restrict__ Y, int N) {
    extern __shared__ char smem[];
    __nv_bfloat16* Wh = (__nv_bfloat16*)(smem);
    __nv_bfloat16* Wl = (__nv_bfloat16*)(smem + WL_OFF);
    __nv_bfloat16* Xh = (__nv_bfloat16*)(smem + XH_OFF);
    __nv_bfloat16* Xl = (__nv_bfloat16*)(smem + XL_OFF);

    int tid = threadIdx.x;
    int lane = tid & 31;
    int wid = tid >> 5;
    uint32_t sbase = smem_u32(smem);

#pragma unroll
    for (int it = 0; it < 8; it++) {
        int n = it * 16 + (tid >> 4);
        int kc = (tid & 15) * 8;
        uint4 vh = *reinterpret_cast<const uint4*>(Gh + n * HID + kc);
        uint4 vl = *reinterpret_cast<const uint4*>(Gl + n * HID + kc);
        *reinterpret_cast<uint4*>(&Wh[n * PK + kc]) = vh;
        *reinterpret_cast<uint4*>(&Wl[n * PK + kc]) = vl;
    }

    int row0 = (wid & 1) * 32;
    int col0 = (wid >> 1) * 32;
    int gr4 = lane >> 2;
    int l2 = (lane & 3) * 2;

    uint32_t aoff = (uint32_t)(((row0 + (lane & 15)) * PK + ((lane >> 4) & 1) * 8) * 2);
    uint32_t boff = (uint32_t)(((col0 + (lane & 7) + ((lane >> 4) & 1) * 8) * PK +
                                ((lane >> 3) & 1) * 8) * 2);

    int ntiles = (N + 63) >> 6;
#pragma unroll 1
    for (int t = blockIdx.x; t < ntiles; t += gridDim.x) {
        int rb = t * 64;
        __syncthreads();
#pragma unroll
        for (int it = 0; it < 8; it++) {
            int r = it * 8 + (tid >> 5);
            int gr = rb + r;
            int kc = (tid & 31) * 4;
            float4 x = (gr < N) ? *reinterpret_cast<const float4*>(X + (size_t)gr * HID + kc)
                                : make_float4(0.f, 0.f, 0.f, 0.f);
            uint2 hi, lo;
            split4(x, hi, lo);
            *reinterpret_cast<uint2*>(&Xh[r * PK + kc]) = hi;
            *reinterpret_cast<uint2*>(&Xl[r * PK + kc]) = lo;
        }
        __syncthreads();

        float acc[2][4][4];
#pragma unroll
        for (int mt = 0; mt < 2; mt++)
#pragma unroll
            for (int nt = 0; nt < 4; nt++)
#pragma unroll
                for (int j = 0; j < 4; j++) acc[mt][nt][j] = 0.f;

#pragma unroll
        for (int ks = 0; ks < 8; ks++) {
            uint32_t kb = ks * 32;
            uint32_t ah[2][4], al[2][4], bh[4][2], bl[4][2];
            uint32_t aXh = sbase + XH_OFF + aoff + kb;
            uint32_t aXl = sbase + XL_OFF + aoff + kb;
            ldsm_x4(ah[0], aXh);
            ldsm_x4(ah[1], aXh + 16 * PK * 2);
            ldsm_x4(al[0], aXl);
            ldsm_x4(al[1], aXl + 16 * PK * 2);
            uint32_t bWh = sbase + boff + kb;
            uint32_t bWl = sbase + WL_OFF + boff + kb;
            ldsm_x4(&bh[0][0], bWh);
            ldsm_x4(&bh[2][0], bWh + 16 * PK * 2);
            ldsm_x4(&bl[0][0], bWl);
            ldsm_x4(&bl[2][0], bWl + 16 * PK * 2);
#pragma unroll
            for (int mt = 0; mt < 2; mt++)
#pragma unroll
                for (int nt = 0; nt < 4; nt++) {
                    mma16816(acc[mt][nt], ah[mt], bh[nt]);
                    mma16816(acc[mt][nt], ah[mt], bl[nt]);
                    mma16816(acc[mt][nt], al[mt], bh[nt]);
                }
        }

#pragma unroll
        for (int nt = 0; nt < 4; nt++) {
            int c = col0 + nt * 8 + l2;
            float bx = bias[c], by = bias[c + 1];
#pragma unroll
            for (int mt = 0; mt < 2; mt++) {
                int r0 = rb + row0 + mt * 16 + gr4;
                if (r0 < N) {
                    float2 v = make_float2(acc[mt][nt][0] + bx, acc[mt][nt][1] + by);
                    *reinterpret_cast<float2*>(Y + (size_t)r0 * HID + c) = v;
                }
                if (r0 + 8 < N) {
                    float2 v = make_float2(acc[mt][nt][2] + bx, acc[mt][nt][3] + by);
                    *reinterpret_cast<float2*>(Y + (size_t)(r0 + 8) * HID + c) = v;
                }
            }
        }
    }
}

// ---------------- merged input projection ----------------
__global__ void proj_both_kernel(const float* __restrict__ Xn, const float* __restrict__ Wn,
                                 const float* __restrict__ bn, float* __restrict__ Yn,
                                 const float* __restrict__ Xc, const float* __restrict__ Wc,
                                 const float* __restrict__ bc, float* __restrict__ Yc) {
    __shared__ float xs[64];
    int blk = blockIdx.x;
    int n = threadIdx.x;  // 128 threads
    const float* X;
    const float* W;
    const float* b;
    float* Y;
    int row, K;
    if (blk < NN) {
        X = Xn; W = Wn; b = bn; Y = Yn; row = blk; K = ND;
    } else {
        X = Xc; W = Wc; b = bc; Y = Yc; row = blk - NN; K = CD;
    }
    if (n < K) xs[n] = X[(size_t)row * K + n];
    __syncthreads();
    float acc = b[n];
    for (int k = 0; k < K; k++) acc = fmaf(xs[k], W[k * HID + n], acc);
    Y[(size_t)row * HID + n] = acc;
}

// ---------------- CSR build ----------------
__global__ void build_zero_kernel(int* __restrict__ dm, int* __restrict__ dc) {
    int i = blockIdx.x * blockDim.x + threadIdx.x;
    if (i < NC) dm[i] = 0;
    if (i < NN) dc[i] = 0;
}
__global__ void build_hist_kernel(const int* __restrict__ mdst, const int* __restrict__ cdst,
                                  int* __restrict__ dm, int* __restrict__ dc, int E) {
    int i = blockIdx.x * blockDim.x + threadIdx.x;
    if (i < E)
        atomicAdd(&dm[mdst[i]], 1);
    else if (i < 2 * E)
        atomicAdd(&dc[cdst[i - E]], 1);
}
__global__ void scanA_kernel(const int* __restrict__ dm, const int* __restrict__ dc,
                             int* __restrict__ part) {
    int b = blockIdx.x;
    const int* deg;
    int n, c0;
    if (b < NB_M) { deg = dm; n = NC; c0 = b * SCHUNK; }
    else          { deg = dc; n = NN; c0 = (b - NB_M) * SCHUNK; }
    int t = threadIdx.x;
    int base = c0 + t * 8;
    int s = 0;
#pragma unroll
    for (int i = 0; i < 8; i++) {
        int idx = base + i;
        if (idx < n) s += deg[idx];
    }
#pragma unroll
    for (int o = 16; o > 0; o >>= 1) s += __shfl_xor_sync(0xffffffffu, s, o);
    __shared__ int red[8];
    if ((t & 31) == 0) red[t >> 5] = s;
    __syncthreads();
    if (t == 0) {
        int tot = 0;
#pragma unroll
        for (int i = 0; i < 8; i++) tot += red[i];
        part[b] = tot;
    }
}
__global__ void scanB_kernel(int* __restrict__ part, int* __restrict__ om,
                             int* __restrict__ oc, int E) {
    __shared__ int sm_[128];
    int t = threadIdx.x;  // 128
    sm_[t] = (t < NB_T) ? part[t] : 0;
    __syncthreads();
    if (t == 0) {
        int run = 0;
        for (int i = 0; i < NB_M; i++) { int x = sm_[i]; sm_[i] = run; run += x; }
        run = 0;
        for (int i = NB_M; i < NB_T; i++) { int x = sm_[i]; sm_[i] = run; run += x; }
        om[NC] = E;
        oc[NN] = E;
    }
    __syncthreads();
    if (t < NB_T) part[t] = sm_[t];
}
__global__ void scanC_kernel(const int* __restrict__ dm, const int* __restrict__ dc,
                             const int* __restrict__ part, int* __restrict__ om,
                             int* __restrict__ oc, int* __restrict__ cm,
                             int* __restrict__ cc) {
    int b = blockIdx.x;
    const int* deg;
    int *off, *cur;
    int n, c0;
    if (b < NB_M) { deg = dm; off = om; cur = cm; n = NC; c0 = b * SCHUNK; }
    else          { deg = dc; off = oc; cur = cc; n = NN; c0 = (b - NB_M) * SCHUNK; }
    int t = threadIdx.x;  // 256
    int base = c0 + t * 8;
    int v[8];
    int s = 0;
#pragma unroll
    for (int i = 0; i < 8; i++) {
        int idx = base + i;
        v[i] = (idx < n) ? deg[idx] : 0;
        s += v[i];
    }
    int lane = t & 31, w = t >> 5;
    int pre = s;
#pragma unroll
    for (int o = 1; o < 32; o <<= 1) {
        int u = __shfl_up_sync(0xffffffffu, pre, o);
        if (lane >= o) pre += u;
    }
    __shared__ int wsum[8];
    if (lane == 31) wsum[w] = pre;
    __syncthreads();
    if (t == 0) {
        int run = 0;
#pragma unroll
        for (int i = 0; i < 8; i++) { int x = wsum[i]; wsum[i] = run; run += x; }
    }
    __syncthreads();
    int ex = pre - s + wsum[w] + part[b];
#pragma unroll
    for (int i = 0; i < 8; i++) {
        int idx = base + i;
        if (idx < n) {
            off[idx] = ex;
            cur[idx] = ex;
            ex += v[i];
        }
    }
}
__global__ void build_scatter_kernel(const int* __restrict__ msrc, const int* __restrict__ mdst,
                                     const int* __restrict__ csrc_e, const int* __restrict__ cdst,
                                     int* __restrict__ cm, int* __restrict__ cc,
                                     int* __restrict__ sm, int* __restrict__ sc, int E) {
    int i = blockIdx.x * blockDim.x + threadIdx.x;
    if (i < E) {
        int p = atomicAdd(&cm[mdst[i]], 1);
        sm[p] = msrc[i];
    } else if (i < 2 * E) {
        int j = i - E;
        int p = atomicAdd(&cc[cdst[j]], 1);
        sc[p] = csrc_e[j];
    }
}

// ---------------- fused GATv2: 4-edge online softmax + LN (+optional mean) ----------
__device__ __forceinline__ float edge_score(float4 xl4, float4 xr4, float4 at4) {
    float vx = xl4.x + xr4.x; vx = vx > 0.f ? vx : SLOPE * vx;
    float vy = xl4.y + xr4.y; vy = vy > 0.f ? vy : SLOPE * vy;
    float vz = xl4.z + xr4.z; vz = vz > 0.f ? vz : SLOPE * vz;
    float vw = xl4.w + xr4.w; vw = vw > 0.f ? vw : SLOPE * vw;
    float sc = vx * at4.x + vy * at4.y + vz * at4.z + vw * at4.w;
    sc += __shfl_xor_sync(0xffffffffu, sc, 1);
    sc += __shfl_xor_sync(0xffffffffu, sc, 2);
    sc += __shfl_xor_sync(0xffffffffu, sc, 4);
    return sc;
}

// mean_out == nullptr: write LN result to x. Otherwise: skip x store, block-reduce
// o into smem and atomically accumulate column mean into mean_out (scaled 1/n_dst).
// NOTE: grids are exact (n_dst*32 divisible by 256) -> no early-exit warps.
__global__ void gat_kernel(const int* __restrict__ off, const int* __restrict__ csrc,
                           const float* __restrict__ xl, const float* __restrict__ xr,
                           const float* __restrict__ att, const float* __restrict__ bias,
                           const float* __restrict__ lng, const float* __restrict__ lnb,
                           float* __restrict__ x, int n_dst, float* __restrict__ mean_out) {
    __shared__ float blk[128];
    int d = (blockIdx.x * blockDim.x + threadIdx.x) >> 5;
    if (d >= n_dst) return;
    int l = threadIdx.x & 31;
    int ofs = l * 4;

    float4 xr4 = *(const float4*)(xr + (size_t)d * HID + ofs);
    float4 at4 = *(const float4*)(att + ofs);
    int e0 = off[d], e1 = off[d + 1];

    float m = -1e30f, den = 0.f;
    float4 acc = make_float4(0.f, 0.f, 0.f, 0.f);

    for (int e = e0; e < e1; e += 4) {
        int ns = e1 - e;
        int s0 = csrc[e];
        int s1 = (ns > 1) ? csrc[e + 1] : s0;
        int s2 = (ns > 2) ? csrc[e + 2] : s0;
        int s3 = (ns > 3) ? csrc[e + 3] : s0;
        float4 v0 = *(const float4*)(xl + (size_t)s0 * HID + ofs);
        float4 v1 = *(const float4*)(xl + (size_t)s1 * HID + ofs);
        float4 v2 = *(const float4*)(xl + (size_t)s2 * HID + ofs);
        float4 v3 = *(const float4*)(xl + (size_t)s3 * HID + ofs);
        float sc0 = edge_score(v0, xr4, at4);
        float sc1 = edge_score(v1, xr4, at4);
        float sc2 = edge_score(v2, xr4, at4);
        float sc3 = edge_score(v3, xr4, at4);
        if (ns < 4) sc3 = -1e30f;
        if (ns < 3) sc2 = -1e30f;
        if (ns < 2) sc1 = -1e30f;
        float gm = fmaxf(fmaxf(sc0, sc1), fmaxf(sc2, sc3));
        float nm = fmaxf(m, gm);
        float f = __expf(m - nm);
        float e0x = __expf(sc0 - nm);
        float e1x = __expf(sc1 - nm);
        float e2x = __expf(sc2 - nm);
        float e3x = __expf(sc3 - nm);
        den = den * f + ((e0x + e1x) + (e2x + e3x));
        acc.x = acc.x * f + (fmaf(e0x, v0.x, e1x * v1.x) + fmaf(e2x, v2.x, e3x * v3.x));
        acc.y = acc.y * f + (fmaf(e0x, v0.y, e1x * v1.y) + fmaf(e2x, v2.y, e3x * v3.y));
        acc.z = acc.z * f + (fmaf(e0x, v0.z, e1x * v1.z) + fmaf(e2x, v2.z, e3x * v3.z));
        acc.w = acc.w * f + (fmaf(e0x, v0.w, e1x * v1.w) + fmaf(e2x, v2.w, e3x * v3.w));
        m = nm;
    }

    float inv = (e1 > e0) ? 1.0f / den : 0.0f;
    float4 b4 = *(const float4*)(bias + ofs);
    float4 x4 = *(const float4*)(x + (size_t)d * HID + ofs);
    float4 o;
    o.x = acc.x * inv + b4.x + x4.x;
    o.y = acc.y * inv + b4.y + x4.y;
    o.z = acc.z * inv + b4.z + x4.z;
    o.w = acc.w * inv + b4.w + x4.w;

    float s = o.x + o.y + o.z + o.w;
#pragma unroll
    for (int k = 16; k > 0; k >>= 1) s += __shfl_xor_sync(0xffffffffu, s, k);
    float mu = s * (1.0f / HID);
    float q = (o.x - mu) * (o.x - mu) + (o.y - mu) * (o.y - mu) +
              (o.z - mu) * (o.z - mu) + (o.w - mu) * (o.w - mu);
#pragma unroll
    for (int k = 16; k > 0; k >>= 1) q += __shfl_xor_sync(0xffffffffu, q, k);
    float rs = rsqrtf(q * (1.0f / HID) + LNEPS);
    float4 g4 = *(const float4*)(lng + ofs);
    float4 bb4 = *(const float4*)(lnb + ofs);
    o.x = (o.x - mu) * rs * g4.x + bb4.x;
    o.y = (o.y - mu) * rs * g4.y + bb4.y;
    o.z = (o.z - mu) * rs * g4.z + bb4.z;
    o.w = (o.w - mu) * rs * g4.w + bb4.w;

    if (mean_out == nullptr) {
        *(float4*)(x + (size_t)d * HID + ofs) = o;
    } else {
        if (threadIdx.x < 128) blk[threadIdx.x] = 0.f;
        __syncthreads();
        atomicAdd(&blk[ofs + 0], o.x);
        atomicAdd(&blk[ofs + 1], o.y);
        atomicAdd(&blk[ofs + 2], o.z);
        atomicAdd(&blk[ofs + 3], o.w);
        __syncthreads();
        if (threadIdx.x < 128)
            atomicAdd(&mean_out[threadIdx.x], blk[threadIdx.x] * (1.0f / n_dst));
    }
}

// ---------------- output zero ----------------
__global__ void zero_out_kernel(float* __restrict__ out) { out[threadIdx.x] = 0.0f; }

// ---------------- host orchestration ----------------
static inline int ceil_div(int a, int b) { return (a + b - 1) / b; }

extern "C" void kernel_launch(void* const* d_in, const int* in_sizes, int n_in,
                              void* d_out, int out_size) {
    const float* x_node       = (const float*)d_in[0];
    const float* x_class      = (const float*)d_in[1];
    const int*   member_src   = (const int*)d_in[2];
    const int*   member_dst   = (const int*)d_in[3];
    const int*   contains_src = (const int*)d_in[4];
    const int*   contains_dst = (const int*)d_in[5];
    const float* npw = (const float*)d_in[6];
    const float* npb = (const float*)d_in[7];
    const float* cpw = (const float*)d_in[8];
    const float* cpb = (const float*)d_in[9];
    const float* n2c_wl   = (const float*)d_in[10];
    const float* n2c_bl   = (const float*)d_in[11];
    const float* n2c_wr   = (const float*)d_in[12];
    const float* n2c_br   = (const float*)d_in[13];
    const float* n2c_att  = (const float*)d_in[14];
    const float* n2c_bias = (const float*)d_in[15];
    const float* c2n_wl   = (const float*)d_in[16];
    const float* c2n_bl   = (const float*)d_in[17];
    const float* c2n_wr   = (const float*)d_in[18];
    const float* c2n_br   = (const float*)d_in[19];
    const float* c2n_att  = (const float*)d_in[20];
    const float* c2n_bias = (const float*)d_in[21];
    const float* ln_cg = (const float*)d_in[22];
    const float* ln_cb = (const float*)d_in[23];
    const float* ln_ng = (const float*)d_in[24];
    const float* ln_nb = (const float*)d_in[25];
    float* out = (float*)d_out;

    int E = in_sizes[2];

    float *xn, *xc, *xl, *xr, *xl2, *xr2;
    int *deg_m, *cur_m, *deg_c, *cur_c, *off_m, *off_c, *src_m, *src_c, *part;
    __nv_bfloat16 *wth, *wtl;
    cudaGetSymbolAddress((void**)&xn, g_xn);
    cudaGetSymbolAddress((void**)&xc, g_xc);
    cudaGetSymbolAddress((void**)&xl, g_xl);
    cudaGetSymbolAddress((void**)&xr, g_xr);
    cudaGetSymbolAddress((void**)&xl2, g_xl2);
    cudaGetSymbolAddress((void**)&xr2, g_xr2);
    cudaGetSymbolAddress((void**)&deg_m, g_deg_m);
    cudaGetSymbolAddress((void**)&cur_m, g_cur_m);
    cudaGetSymbolAddress((void**)&deg_c, g_deg_c);
    cudaGetSymbolAddress((void**)&cur_c, g_cur_c);
    cudaGetSymbolAddress((void**)&off_m, g_off_m);
    cudaGetSymbolAddress((void**)&off_c, g_off_c);
    cudaGetSymbolAddress((void**)&src_m, g_src_m);
    cudaGetSymbolAddress((void**)&src_c, g_src_c);
    cudaGetSymbolAddress((void**)&part, g_part);
    cudaGetSymbolAddress((void**)&wth, g_wth);
    cudaGetSymbolAddress((void**)&wtl, g_wtl);

    cudaFuncSetAttribute(mm_gemm_p, cudaFuncAttributeMaxDynamicSharedMemorySize, MM_SMEM);

    // side streams + fork/join events (created once; host-side only)
    static cudaStream_t s1 = nullptr, s2 = nullptr;
    static cudaEvent_t ev[8];
    if (s1 == nullptr) {
        cudaStreamCreateWithFlags(&s1, cudaStreamNonBlocking);
        cudaStreamCreateWithFlags(&s2, cudaStreamNonBlocking);
        for (int i = 0; i < 8; i++) cudaEventCreateWithFlags(&ev[i], cudaEventDisableTiming);
    }

    int g2E = ceil_div(2 * E, 256);
    const size_t WSZ = (size_t)HID * HID;

    // fork CSR build onto s2 immediately (depends only on edge lists)
    cudaEventRecord(ev[6], 0);
    cudaStreamWaitEvent(s2, ev[6], 0);
    build_zero_kernel<<<ceil_div(NN, 256), 256, 0, s2>>>(deg_m, deg_c);
    build_hist_kernel<<<g2E, 256, 0, s2>>>(member_dst, contains_dst, deg_m, deg_c, E);
    scanA_kernel<<<NB_T, 256, 0, s2>>>(deg_m, deg_c, part);
    scanB_kernel<<<1, 128, 0, s2>>>(part, off_m, off_c, E);
    scanC_kernel<<<NB_T, 256, 0, s2>>>(deg_m, deg_c, part, off_m, off_c, cur_m, cur_c);
    build_scatter_kernel<<<g2E, 256, 0, s2>>>(member_src, member_dst, contains_src,
                                              contains_dst, cur_m, cur_c, src_m, src_c, E);
    cudaEventRecord(ev[7], s2);  // CSR done

    // s0: weight prep + input projections
    prep_weights_kernel<<<16, 256>>>(n2c_wl, n2c_wr, c2n_wl, c2n_wr, wth, wtl);
    proj_both_kernel<<<NN + NC, 128>>>(x_node, npw, npb, xn, x_class, cpw, cpb, xc);
    zero_out_kernel<<<1, 128>>>(out);

    // fork: xr = xc @ n2c_wr[0] on s1; xl = xn @ n2c_wl[0] on s0
    cudaEventRecord(ev[0], 0);
    cudaStreamWaitEvent(s1, ev[0], 0);
    mm_gemm_p<<<GRIDP, 256, MM_SMEM, s1>>>(xc, wth + (1 * 4 + 0) * WSZ,
                                           wtl + (1 * 4 + 0) * WSZ, n2c_br, xr, NC);
    cudaEventRecord(ev[1], s1);
    mm_gemm_p<<<GRIDP, 256, MM_SMEM>>>(xn, wth + (0 * 4 + 0) * WSZ,
                                       wtl + (0 * 4 + 0) * WSZ, n2c_bl, xl, NN);
    cudaStreamWaitEvent(0, ev[1], 0);  // join: xr ready
    cudaStreamWaitEvent(0, ev[7], 0);  // join: CSR ready

    for (int l = 0; l < NL; l++) {
        bool last = (l == NL - 1);
        if (!last) {
            // fork: xr2 = xn @ c2n_wr[l] (independent of gat_n2c)
            cudaEventRecord(ev[2], 0);
            cudaStreamWaitEvent(s1, ev[2], 0);
            mm_gemm_p<<<GRIDP, 256, MM_SMEM, s1>>>(xn, wth + (3 * 4 + l) * WSZ,
                                                   wtl + (3 * 4 + l) * WSZ,
                                                   c2n_br + l * HID, xr2, NN);
            cudaEventRecord(ev[3], s1);
        }
        gat_kernel<<<ceil_div(NC * 32, 256), 256>>>(
            off_m, src_m, xl, xr, n2c_att + l * HID, n2c_bias + l * HID,
            ln_cg + l * HID, ln_cb + l * HID, xc, NC, last ? out : nullptr);
        if (last) break;  // layer-3 c2n is dead work (output depends only on xc)

        // fork: xr(next) = xc @ n2c_wr[l+1] (needs updated xc; overlaps gat_c2n)
        cudaEventRecord(ev[4], 0);
        cudaStreamWaitEvent(s1, ev[4], 0);
        mm_gemm_p<<<GRIDP, 256, MM_SMEM, s1>>>(xc, wth + (1 * 4 + (l + 1)) * WSZ,
                                               wtl + (1 * 4 + (l + 1)) * WSZ,
                                               n2c_br + (l + 1) * HID, xr, NC);
        cudaEventRecord(ev[5], s1);

        // s0: xl2 = xc @ c2n_wl[l]
        mm_gemm_p<<<GRIDP, 256, MM_SMEM>>>(xc, wth + (2 * 4 + l) * WSZ,
                                           wtl + (2 * 4 + l) * WSZ,
                                           c2n_bl + l * HID, xl2, NC);
        cudaStreamWaitEvent(0, ev[3], 0);  // join: xr2 ready
        gat_kernel<<<ceil_div(NN * 32, 256), 256>>>(
            off_c, src_c, xl2, xr2, c2n_att + l * HID, c2n_bias + l * HID,
            ln_ng + l * HID, ln_nb + l * HID, xn, NN, nullptr);
        // s0: xl(next) = xn @ n2c_wl[l+1]
        mm_gemm_p<<<GRIDP, 256, MM_SMEM>>>(xn, wth + (0 * 4 + (l + 1)) * WSZ,
                                           wtl + (0 * 4 + (l + 1)) * WSZ,
                                           n2c_bl + (l + 1) * HID, xl, NN);
        cudaStreamWaitEvent(0, ev[5], 0);  // join: xr(next) ready
    }
}

// round 14
// speedup vs baseline: 1.1389x; 1.0534x over previous
#include <cuda_runtime.h>
#include <cuda_bf16.h>
#include <math.h>
#include <cstdint>

// ---------------- problem constants ----------------
#define NN 100000
#define NC 50000
#define EE 400000
#define ND 43
#define CD 2
#define HID 128
#define NL 4
#define SLOPE 0.2f
#define LNEPS 1e-5f

#define SCHUNK 2048
#define NB_M ((NC + SCHUNK - 1) / SCHUNK)   // 25
#define NB_C ((NN + SCHUNK - 1) / SCHUNK)   // 49
#define NB_T (NB_M + NB_C)                  // 74

// padded K stride for smem tiles (conflict-free ldmatrix rows)
#define PK 136
#define W_BYTES (128 * PK * 2)              // 34816 per W tile (hi or lo)
#define X_BYTES (64 * PK * 2)               // 17408 per X tile (hi or lo)
#define MM_SMEM (2 * W_BYTES + 2 * X_BYTES) // 104448 -> 2 blocks/SM
#define XH_OFF (2 * W_BYTES)
#define XL_OFF (2 * W_BYTES + X_BYTES)
#define WL_OFF (W_BYTES)
#define GRIDP 296                            // 2 blocks/SM x 148 SMs

// ---------------- device scratch (static, no allocation) ----------------
__device__ float g_xn[(size_t)NN * HID];
__device__ float g_xc[(size_t)NC * HID];
__device__ float g_xl[(size_t)NN * HID];    // n2c wl output (NN rows)
__device__ float g_xr[(size_t)NC * HID];    // n2c wr output (NC rows)
__device__ float g_xl2[(size_t)NC * HID];   // c2n wl output (NC rows)
__device__ float g_xr2[(size_t)NN * HID];   // c2n wr output (NN rows)
__device__ int g_deg_m[NC];
__device__ int g_cur_m[NC];
__device__ int g_deg_c[NN];
__device__ int g_cur_c[NN];
__device__ int g_off_m[NC + 1];
__device__ int g_off_c[NN + 1];
__device__ int g_src_m[EE];
__device__ int g_src_c[EE];
__device__ int g_part[128];
// transposed+split weights: 16 matrices [n][k] bf16 (idx = group*4 + layer)
__device__ __nv_bfloat16 g_wth[16 * HID * HID];
__device__ __nv_bfloat16 g_wtl[16 * HID * HID];

// ---------------- helpers ----------------
__device__ __forceinline__ void mma16816(float* d, const uint32_t* a, const uint32_t* b) {
    asm volatile(
        "mma.sync.aligned.m16n8k16.row.col.f32.bf16.bf16.f32 "
        "{%0,%1,%2,%3}, {%4,%5,%6,%7}, {%8,%9}, {%0,%1,%2,%3};"
        : "+f"(d[0]), "+f"(d[1]), "+f"(d[2]), "+f"(d[3])
        : "r"(a[0]), "r"(a[1]), "r"(a[2]), "r"(a[3]), "r"(b[0]), "r"(b[1]));
}
__device__ __forceinline__ void ldsm_x4(uint32_t* r, uint32_t addr) {
    asm volatile("ldmatrix.sync.aligned.m8n8.x4.shared.b16 {%0,%1,%2,%3}, [%4];"
                 : "=r"(r[0]), "=r"(r[1]), "=r"(r[2]), "=r"(r[3])
                 : "r"(addr));
}
__device__ __forceinline__ uint32_t smem_u32(const void* p) {
    uint32_t a;
    asm("{ .reg .u64 t; cvta.to.shared.u64 t, %1; cvt.u32.u64 %0, t; }" : "=r"(a) : "l"(p));
    return a;
}
__device__ __forceinline__ void split4(float4 x, uint2& hi, uint2& lo) {
    __nv_bfloat162 h01 = __floats2bfloat162_rn(x.x, x.y);
    __nv_bfloat162 h23 = __floats2bfloat162_rn(x.z, x.w);
    float r0 = x.x - __low2float(h01);
    float r1 = x.y - __high2float(h01);
    float r2 = x.z - __low2float(h23);
    float r3 = x.w - __high2float(h23);
    __nv_bfloat162 l01 = __floats2bfloat162_rn(r0, r1);
    __nv_bfloat162 l23 = __floats2bfloat162_rn(r2, r3);
    hi.x = *reinterpret_cast<uint32_t*>(&h01);
    hi.y = *reinterpret_cast<uint32_t*>(&h23);
    lo.x = *reinterpret_cast<uint32_t*>(&l01);
    lo.y = *reinterpret_cast<uint32_t*>(&l23);
}

// ---------------- weight prep: transpose + bf16 split (16 matrices) ----------------
__global__ void prep_weights_kernel(const float* __restrict__ n2c_wl,
                                    const float* __restrict__ n2c_wr,
                                    const float* __restrict__ c2n_wl,
                                    const float* __restrict__ c2n_wr,
                                    __nv_bfloat16* __restrict__ wth,
                                    __nv_bfloat16* __restrict__ wtl) {
    int idx = blockIdx.x;  // 0..15
    int grp = idx >> 2, lay = idx & 3;
    const float* W = (grp == 0) ? n2c_wl : (grp == 1) ? n2c_wr : (grp == 2) ? c2n_wl : c2n_wr;
    W += (size_t)lay * HID * HID;
    __nv_bfloat16* oh = wth + (size_t)idx * HID * HID;
    __nv_bfloat16* ol = wtl + (size_t)idx * HID * HID;
    for (int e = threadIdx.x; e < HID * HID; e += blockDim.x) {
        int k = e >> 7, n = e & 127;
        float w = W[e];  // W[k][n]
        __nv_bfloat16 h = __float2bfloat16_rn(w);
        float r = w - __bfloat162float(h);
        oh[n * HID + k] = h;
        ol[n * HID + k] = __float2bfloat16_rn(r);
    }
}

// ---------------- persistent HMMA GEMM: Y[N,128] = X[N,128] @ W + b ------------------
__global__ void __launch_bounds__(256, 2)
mm_gemm_p(const float* __restrict__ X, const __nv_bfloat16* __restrict__ Gh,
          const __nv_bfloat16* __restrict__ Gl, const float* __restrict__ bias,
          float* __restrict__ Y, int N) {
    extern __shared__ char smem[];
    __nv_bfloat16* Wh = (__nv_bfloat16*)(smem);
    __nv_bfloat16* Wl = (__nv_bfloat16*)(smem + WL_OFF);
    __nv_bfloat16* Xh = (__nv_bfloat16*)(smem + XH_OFF);
    __nv_bfloat16* Xl = (__nv_bfloat16*)(smem + XL_OFF);

    int tid = threadIdx.x;
    int lane = tid & 31;
    int wid = tid >> 5;
    uint32_t sbase = smem_u32(smem);

#pragma unroll
    for (int it = 0; it < 8; it++) {
        int n = it * 16 + (tid >> 4);
        int kc = (tid & 15) * 8;
        uint4 vh = *reinterpret_cast<const uint4*>(Gh + n * HID + kc);
        uint4 vl = *reinterpret_cast<const uint4*>(Gl + n * HID + kc);
        *reinterpret_cast<uint4*>(&Wh[n * PK + kc]) = vh;
        *reinterpret_cast<uint4*>(&Wl[n * PK + kc]) = vl;
    }

    int row0 = (wid & 1) * 32;
    int col0 = (wid >> 1) * 32;
    int gr4 = lane >> 2;
    int l2 = (lane & 3) * 2;

    uint32_t aoff = (uint32_t)(((row0 + (lane & 15)) * PK + ((lane >> 4) & 1) * 8) * 2);
    uint32_t boff = (uint32_t)(((col0 + (lane & 7) + ((lane >> 4) & 1) * 8) * PK +
                                ((lane >> 3) & 1) * 8) * 2);

    int ntiles = (N + 63) >> 6;
#pragma unroll 1
    for (int t = blockIdx.x; t < ntiles; t += gridDim.x) {
        int rb = t * 64;
        __syncthreads();
#pragma unroll
        for (int it = 0; it < 8; it++) {
            int r = it * 8 + (tid >> 5);
            int gr = rb + r;
            int kc = (tid & 31) * 4;
            float4 x = (gr < N) ? *reinterpret_cast<const float4*>(X + (size_t)gr * HID + kc)
                                : make_float4(0.f, 0.f, 0.f, 0.f);
            uint2 hi, lo;
            split4(x, hi, lo);
            *reinterpret_cast<uint2*>(&Xh[r * PK + kc]) = hi;
            *reinterpret_cast<uint2*>(&Xl[r * PK + kc]) = lo;
        }
        __syncthreads();

        float acc[2][4][4];
#pragma unroll
        for (int mt = 0; mt < 2; mt++)
#pragma unroll
            for (int nt = 0; nt < 4; nt++)
#pragma unroll
                for (int j = 0; j < 4; j++) acc[mt][nt][j] = 0.f;

#pragma unroll
        for (int ks = 0; ks < 8; ks++) {
            uint32_t kb = ks * 32;
            uint32_t ah[2][4], al[2][4], bh[4][2], bl[4][2];
            uint32_t aXh = sbase + XH_OFF + aoff + kb;
            uint32_t aXl = sbase + XL_OFF + aoff + kb;
            ldsm_x4(ah[0], aXh);
            ldsm_x4(ah[1], aXh + 16 * PK * 2);
            ldsm_x4(al[0], aXl);
            ldsm_x4(al[1], aXl + 16 * PK * 2);
            uint32_t bWh = sbase + boff + kb;
            uint32_t bWl = sbase + WL_OFF + boff + kb;
            ldsm_x4(&bh[0][0], bWh);
            ldsm_x4(&bh[2][0], bWh + 16 * PK * 2);
            ldsm_x4(&bl[0][0], bWl);
            ldsm_x4(&bl[2][0], bWl + 16 * PK * 2);
#pragma unroll
            for (int mt = 0; mt < 2; mt++)
#pragma unroll
                for (int nt = 0; nt < 4; nt++) {
                    mma16816(acc[mt][nt], ah[mt], bh[nt]);
                    mma16816(acc[mt][nt], ah[mt], bl[nt]);
                    mma16816(acc[mt][nt], al[mt], bh[nt]);
                }
        }

#pragma unroll
        for (int nt = 0; nt < 4; nt++) {
            int c = col0 + nt * 8 + l2;
            float bx = bias[c], by = bias[c + 1];
#pragma unroll
            for (int mt = 0; mt < 2; mt++) {
                int r0 = rb + row0 + mt * 16 + gr4;
                if (r0 < N) {
                    float2 v = make_float2(acc[mt][nt][0] + bx, acc[mt][nt][1] + by);
                    *reinterpret_cast<float2*>(Y + (size_t)r0 * HID + c) = v;
                }
                if (r0 + 8 < N) {
                    float2 v = make_float2(acc[mt][nt][2] + bx, acc[mt][nt][3] + by);
                    *reinterpret_cast<float2*>(Y + (size_t)(r0 + 8) * HID + c) = v;
                }
            }
        }
    }
}

// ---------------- merged input projection ----------------
__global__ void proj_both_kernel(const float* __restrict__ Xn, const float* __restrict__ Wn,
                                 const float* __restrict__ bn, float* __restrict__ Yn,
                                 const float* __restrict__ Xc, const float* __restrict__ Wc,
                                 const float* __restrict__ bc, float* __restrict__ Yc) {
    __shared__ float xs[64];
    int blk = blockIdx.x;
    int n = threadIdx.x;  // 128 threads
    const float* X;
    const float* W;
    const float* b;
    float* Y;
    int row, K;
    if (blk < NN) {
        X = Xn; W = Wn; b = bn; Y = Yn; row = blk; K = ND;
    } else {
        X = Xc; W = Wc; b = bc; Y = Yc; row = blk - NN; K = CD;
    }
    if (n < K) xs[n] = X[(size_t)row * K + n];
    __syncthreads();
    float acc = b[n];
    for (int k = 0; k < K; k++) acc = fmaf(xs[k], W[k * HID + n], acc);
    Y[(size_t)row * HID + n] = acc;
}

// ---------------- CSR build ----------------
__global__ void build_zero_kernel(int* __restrict__ dm, int* __restrict__ dc) {
    int i = blockIdx.x * blockDim.x + threadIdx.x;
    if (i < NC) dm[i] = 0;
    if (i < NN) dc[i] = 0;
}
__global__ void build_hist_kernel(const int* __restrict__ mdst, const int* __restrict__ cdst,
                                  int* __restrict__ dm, int* __restrict__ dc, int E) {
    int i = blockIdx.x * blockDim.x + threadIdx.x;
    if (i < E)
        atomicAdd(&dm[mdst[i]], 1);
    else if (i < 2 * E)
        atomicAdd(&dc[cdst[i - E]], 1);
}
__global__ void scanA_kernel(const int* __restrict__ dm, const int* __restrict__ dc,
                             int* __restrict__ part) {
    int b = blockIdx.x;
    const int* deg;
    int n, c0;
    if (b < NB_M) { deg = dm; n = NC; c0 = b * SCHUNK; }
    else          { deg = dc; n = NN; c0 = (b - NB_M) * SCHUNK; }
    int t = threadIdx.x;
    int base = c0 + t * 8;
    int s = 0;
#pragma unroll
    for (int i = 0; i < 8; i++) {
        int idx = base + i;
        if (idx < n) s += deg[idx];
    }
#pragma unroll
    for (int o = 16; o > 0; o >>= 1) s += __shfl_xor_sync(0xffffffffu, s, o);
    __shared__ int red[8];
    if ((t & 31) == 0) red[t >> 5] = s;
    __syncthreads();
    if (t == 0) {
        int tot = 0;
#pragma unroll
        for (int i = 0; i < 8; i++) tot += red[i];
        part[b] = tot;
    }
}
__global__ void scanB_kernel(int* __restrict__ part, int* __restrict__ om,
                             int* __restrict__ oc, int E) {
    __shared__ int sm_[128];
    int t = threadIdx.x;  // 128
    sm_[t] = (t < NB_T) ? part[t] : 0;
    __syncthreads();
    if (t == 0) {
        int run = 0;
        for (int i = 0; i < NB_M; i++) { int x = sm_[i]; sm_[i] = run; run += x; }
        run = 0;
        for (int i = NB_M; i < NB_T; i++) { int x = sm_[i]; sm_[i] = run; run += x; }
        om[NC] = E;
        oc[NN] = E;
    }
    __syncthreads();
    if (t < NB_T) part[t] = sm_[t];
}
__global__ void scanC_kernel(const int* __restrict__ dm, const int* __restrict__ dc,
                             const int* __restrict__ part, int* __restrict__ om,
                             int* __restrict__ oc, int* __restrict__ cm,
                             int* __restrict__ cc) {
    int b = blockIdx.x;
    const int* deg;
    int *off, *cur;
    int n, c0;
    if (b < NB_M) { deg = dm; off = om; cur = cm; n = NC; c0 = b * SCHUNK; }
    else          { deg = dc; off = oc; cur = cc; n = NN; c0 = (b - NB_M) * SCHUNK; }
    int t = threadIdx.x;  // 256
    int base = c0 + t * 8;
    int v[8];
    int s = 0;
#pragma unroll
    for (int i = 0; i < 8; i++) {
        int idx = base + i;
        v[i] = (idx < n) ? deg[idx] : 0;
        s += v[i];
    }
    int lane = t & 31, w = t >> 5;
    int pre = s;
#pragma unroll
    for (int o = 1; o < 32; o <<= 1) {
        int u = __shfl_up_sync(0xffffffffu, pre, o);
        if (lane >= o) pre += u;
    }
    __shared__ int wsum[8];
    if (lane == 31) wsum[w] = pre;
    __syncthreads();
    if (t == 0) {
        int run = 0;
#pragma unroll
        for (int i = 0; i < 8; i++) { int x = wsum[i]; wsum[i] = run; run += x; }
    }
    __syncthreads();
    int ex = pre - s + wsum[w] + part[b];
#pragma unroll
    for (int i = 0; i < 8; i++) {
        int idx = base + i;
        if (idx < n) {
            off[idx] = ex;
            cur[idx] = ex;
            ex += v[i];
        }
    }
}
__global__ void build_scatter_kernel(const int* __restrict__ msrc, const int* __restrict__ mdst,
                                     const int* __restrict__ csrc_e, const int* __restrict__ cdst,
                                     int* __restrict__ cm, int* __restrict__ cc,
                                     int* __restrict__ sm, int* __restrict__ sc, int E) {
    int i = blockIdx.x * blockDim.x + threadIdx.x;
    if (i < E) {
        int p = atomicAdd(&cm[mdst[i]], 1);
        sm[p] = msrc[i];
    } else if (i < 2 * E) {
        int j = i - E;
        int p = atomicAdd(&cc[cdst[j]], 1);
        sc[p] = csrc_e[j];
    }
}

// ---------------- fused GATv2: lane-prefetched 4-edge online softmax + LN ------------
__device__ __forceinline__ float edge_score(float4 xl4, float4 xr4, float4 at4) {
    float vx = xl4.x + xr4.x; vx = vx > 0.f ? vx : SLOPE * vx;
    float vy = xl4.y + xr4.y; vy = vy > 0.f ? vy : SLOPE * vy;
    float vz = xl4.z + xr4.z; vz = vz > 0.f ? vz : SLOPE * vz;
    float vw = xl4.w + xr4.w; vw = vw > 0.f ? vw : SLOPE * vw;
    float sc = vx * at4.x + vy * at4.y + vz * at4.z + vw * at4.w;
    sc += __shfl_xor_sync(0xffffffffu, sc, 1);
    sc += __shfl_xor_sync(0xffffffffu, sc, 2);
    sc += __shfl_xor_sync(0xffffffffu, sc, 4);
    return sc;
}

// mean_out == nullptr: write LN result to x. Otherwise: skip x store, block-reduce
// o into smem and atomically accumulate column mean into mean_out (scaled 1/n_dst).
// NOTE: grids are exact (n_dst*32 divisible by 256) -> no early-exit warps.
__global__ void gat_kernel(const int* __restrict__ off, const int* __restrict__ csrc,
                           const float* __restrict__ xl, const float* __restrict__ xr,
                           const float* __restrict__ att, const float* __restrict__ bias,
                           const float* __restrict__ lng, const float* __restrict__ lnb,
                           float* __restrict__ x, int n_dst, float* __restrict__ mean_out) {
    __shared__ float blk[128];
    int d = (blockIdx.x * blockDim.x + threadIdx.x) >> 5;
    if (d >= n_dst) return;
    int l = threadIdx.x & 31;
    int ofs = l * 4;

    int e0 = off[d], e1 = off[d + 1];
    // independent loads issued up-front (max MLP before the edge chain)
    float4 xr4 = *(const float4*)(xr + (size_t)d * HID + ofs);
    float4 at4 = *(const float4*)(att + ofs);
    float4 x4 = *(const float4*)(x + (size_t)d * HID + ofs);
    float4 b4 = *(const float4*)(bias + ofs);

    float m = -1e30f, den = 0.f;
    float4 acc = make_float4(0.f, 0.f, 0.f, 0.f);

    // windows of 32 edges: ONE coalesced index load per window, shfl-distributed
    for (int w = e0; w < e1; w += 32) {
        int nw = e1 - w;
        if (nw > 32) nw = 32;
        int widx = (w + l < e1) ? csrc[w + l] : 0;
        for (int c = 0; c < nw; c += 4) {
            int ns = nw - c;
            int s0 = __shfl_sync(0xffffffffu, widx, c);
            int s1 = __shfl_sync(0xffffffffu, widx, (ns > 1) ? c + 1 : c);
            int s2 = __shfl_sync(0xffffffffu, widx, (ns > 2) ? c + 2 : c);
            int s3 = __shfl_sync(0xffffffffu, widx, (ns > 3) ? c + 3 : c);
            float4 v0 = *(const float4*)(xl + (size_t)s0 * HID + ofs);
            float4 v1 = *(const float4*)(xl + (size_t)s1 * HID + ofs);
            float4 v2 = *(const float4*)(xl + (size_t)s2 * HID + ofs);
            float4 v3 = *(const float4*)(xl + (size_t)s3 * HID + ofs);
            float sc0 = edge_score(v0, xr4, at4);
            float sc1 = edge_score(v1, xr4, at4);
            float sc2 = edge_score(v2, xr4, at4);
            float sc3 = edge_score(v3, xr4, at4);
            if (ns < 4) sc3 = -1e30f;
            if (ns < 3) sc2 = -1e30f;
            if (ns < 2) sc1 = -1e30f;
            float gm = fmaxf(fmaxf(sc0, sc1), fmaxf(sc2, sc3));
            float nm = fmaxf(m, gm);
            float f = __expf(m - nm);
            float e0x = __expf(sc0 - nm);
            float e1x = __expf(sc1 - nm);
            float e2x = __expf(sc2 - nm);
            float e3x = __expf(sc3 - nm);
            den = den * f + ((e0x + e1x) + (e2x + e3x));
            acc.x = acc.x * f + (fmaf(e0x, v0.x, e1x * v1.x) + fmaf(e2x, v2.x, e3x * v3.x));
            acc.y = acc.y * f + (fmaf(e0x, v0.y, e1x * v1.y) + fmaf(e2x, v2.y, e3x * v3.y));
            acc.z = acc.z * f + (fmaf(e0x, v0.z, e1x * v1.z) + fmaf(e2x, v2.z, e3x * v3.z));
            acc.w = acc.w * f + (fmaf(e0x, v0.w, e1x * v1.w) + fmaf(e2x, v2.w, e3x * v3.w));
            m = nm;
        }
    }

    float inv = (e1 > e0) ? 1.0f / den : 0.0f;
    float4 o;
    o.x = acc.x * inv + b4.x + x4.x;
    o.y = acc.y * inv + b4.y + x4.y;
    o.z = acc.z * inv + b4.z + x4.z;
    o.w = acc.w * inv + b4.w + x4.w;

    float s = o.x + o.y + o.z + o.w;
#pragma unroll
    for (int k = 16; k > 0; k >>= 1) s += __shfl_xor_sync(0xffffffffu, s, k);
    float mu = s * (1.0f / HID);
    float q = (o.x - mu) * (o.x - mu) + (o.y - mu) * (o.y - mu) +
              (o.z - mu) * (o.z - mu) + (o.w - mu) * (o.w - mu);
#pragma unroll
    for (int k = 16; k > 0; k >>= 1) q += __shfl_xor_sync(0xffffffffu, q, k);
    float rs = rsqrtf(q * (1.0f / HID) + LNEPS);
    float4 g4 = *(const float4*)(lng + ofs);
    float4 bb4 = *(const float4*)(lnb + ofs);
    o.x = (o.x - mu) * rs * g4.x + bb4.x;
    o.y = (o.y - mu) * rs * g4.y + bb4.y;
    o.z = (o.z - mu) * rs * g4.z + bb4.z;
    o.w = (o.w - mu) * rs * g4.w + bb4.w;

    if (mean_out == nullptr) {
        *(float4*)(x + (size_t)d * HID + ofs) = o;
    } else {
        if (threadIdx.x < 128) blk[threadIdx.x] = 0.f;
        __syncthreads();
        atomicAdd(&blk[ofs + 0], o.x);
        atomicAdd(&blk[ofs + 1], o.y);
        atomicAdd(&blk[ofs + 2], o.z);
        atomicAdd(&blk[ofs + 3], o.w);
        __syncthreads();
        if (threadIdx.x < 128)
            atomicAdd(&mean_out[threadIdx.x], blk[threadIdx.x] * (1.0f / n_dst));
    }
}

// ---------------- output zero ----------------
__global__ void zero_out_kernel(float* __restrict__ out) { out[threadIdx.x] = 0.0f; }

// ---------------- host orchestration ----------------
static inline int ceil_div(int a, int b) { return (a + b - 1) / b; }

extern "C" void kernel_launch(void* const* d_in, const int* in_sizes, int n_in,
                              void* d_out, int out_size) {
    const float* x_node       = (const float*)d_in[0];
    const float* x_class      = (const float*)d_in[1];
    const int*   member_src   = (const int*)d_in[2];
    const int*   member_dst   = (const int*)d_in[3];
    const int*   contains_src = (const int*)d_in[4];
    const int*   contains_dst = (const int*)d_in[5];
    const float* npw = (const float*)d_in[6];
    const float* npb = (const float*)d_in[7];
    const float* cpw = (const float*)d_in[8];
    const float* cpb = (const float*)d_in[9];
    const float* n2c_wl   = (const float*)d_in[10];
    const float* n2c_bl   = (const float*)d_in[11];
    const float* n2c_wr   = (const float*)d_in[12];
    const float* n2c_br   = (const float*)d_in[13];
    const float* n2c_att  = (const float*)d_in[14];
    const float* n2c_bias = (const float*)d_in[15];
    const float* c2n_wl   = (const float*)d_in[16];
    const float* c2n_bl   = (const float*)d_in[17];
    const float* c2n_wr   = (const float*)d_in[18];
    const float* c2n_br   = (const float*)d_in[19];
    const float* c2n_att  = (const float*)d_in[20];
    const float* c2n_bias = (const float*)d_in[21];
    const float* ln_cg = (const float*)d_in[22];
    const float* ln_cb = (const float*)d_in[23];
    const float* ln_ng = (const float*)d_in[24];
    const float* ln_nb = (const float*)d_in[25];
    float* out = (float*)d_out;

    int E = in_sizes[2];

    float *xn, *xc, *xl, *xr, *xl2, *xr2;
    int *deg_m, *cur_m, *deg_c, *cur_c, *off_m, *off_c, *src_m, *src_c, *part;
    __nv_bfloat16 *wth, *wtl;
    cudaGetSymbolAddress((void**)&xn, g_xn);
    cudaGetSymbolAddress((void**)&xc, g_xc);
    cudaGetSymbolAddress((void**)&xl, g_xl);
    cudaGetSymbolAddress((void**)&xr, g_xr);
    cudaGetSymbolAddress((void**)&xl2, g_xl2);
    cudaGetSymbolAddress((void**)&xr2, g_xr2);
    cudaGetSymbolAddress((void**)&deg_m, g_deg_m);
    cudaGetSymbolAddress((void**)&cur_m, g_cur_m);
    cudaGetSymbolAddress((void**)&deg_c, g_deg_c);
    cudaGetSymbolAddress((void**)&cur_c, g_cur_c);
    cudaGetSymbolAddress((void**)&off_m, g_off_m);
    cudaGetSymbolAddress((void**)&off_c, g_off_c);
    cudaGetSymbolAddress((void**)&src_m, g_src_m);
    cudaGetSymbolAddress((void**)&src_c, g_src_c);
    cudaGetSymbolAddress((void**)&part, g_part);
    cudaGetSymbolAddress((void**)&wth, g_wth);
    cudaGetSymbolAddress((void**)&wtl, g_wtl);

    cudaFuncSetAttribute(mm_gemm_p, cudaFuncAttributeMaxDynamicSharedMemorySize, MM_SMEM);

    // side streams + fork/join events (created once; host-side only)
    static cudaStream_t s1 = nullptr, s2 = nullptr;
    static cudaEvent_t ev[8];
    if (s1 == nullptr) {
        cudaStreamCreateWithFlags(&s1, cudaStreamNonBlocking);
        cudaStreamCreateWithFlags(&s2, cudaStreamNonBlocking);
        for (int i = 0; i < 8; i++) cudaEventCreateWithFlags(&ev[i], cudaEventDisableTiming);
    }

    int g2E = ceil_div(2 * E, 256);
    const size_t WSZ = (size_t)HID * HID;

    // fork CSR build onto s2 immediately (depends only on edge lists)
    cudaEventRecord(ev[6], 0);
    cudaStreamWaitEvent(s2, ev[6], 0);
    build_zero_kernel<<<ceil_div(NN, 256), 256, 0, s2>>>(deg_m, deg_c);
    build_hist_kernel<<<g2E, 256, 0, s2>>>(member_dst, contains_dst, deg_m, deg_c, E);
    scanA_kernel<<<NB_T, 256, 0, s2>>>(deg_m, deg_c, part);
    scanB_kernel<<<1, 128, 0, s2>>>(part, off_m, off_c, E);
    scanC_kernel<<<NB_T, 256, 0, s2>>>(deg_m, deg_c, part, off_m, off_c, cur_m, cur_c);
    build_scatter_kernel<<<g2E, 256, 0, s2>>>(member_src, member_dst, contains_src,
                                              contains_dst, cur_m, cur_c, src_m, src_c, E);
    cudaEventRecord(ev[7], s2);  // CSR done

    // s0: weight prep + input projections
    prep_weights_kernel<<<16, 256>>>(n2c_wl, n2c_wr, c2n_wl, c2n_wr, wth, wtl);
    proj_both_kernel<<<NN + NC, 128>>>(x_node, npw, npb, xn, x_class, cpw, cpb, xc);
    zero_out_kernel<<<1, 128>>>(out);

    // fork: xr = xc @ n2c_wr[0] on s1; xl = xn @ n2c_wl[0] on s0
    cudaEventRecord(ev[0], 0);
    cudaStreamWaitEvent(s1, ev[0], 0);
    mm_gemm_p<<<GRIDP, 256, MM_SMEM, s1>>>(xc, wth + (1 * 4 + 0) * WSZ,
                                           wtl + (1 * 4 + 0) * WSZ, n2c_br, xr, NC);
    cudaEventRecord(ev[1], s1);
    mm_gemm_p<<<GRIDP, 256, MM_SMEM>>>(xn, wth + (0 * 4 + 0) * WSZ,
                                       wtl + (0 * 4 + 0) * WSZ, n2c_bl, xl, NN);
    cudaStreamWaitEvent(0, ev[1], 0);  // join: xr ready
    cudaStreamWaitEvent(0, ev[7], 0);  // join: CSR ready

    for (int l = 0; l < NL; l++) {
        bool last = (l == NL - 1);
        if (!last) {
            // fork: xr2 = xn @ c2n_wr[l] (independent of gat_n2c)
            cudaEventRecord(ev[2], 0);
            cudaStreamWaitEvent(s1, ev[2], 0);
            mm_gemm_p<<<GRIDP, 256, MM_SMEM, s1>>>(xn, wth + (3 * 4 + l) * WSZ,
                                                   wtl + (3 * 4 + l) * WSZ,
                                                   c2n_br + l * HID, xr2, NN);
            cudaEventRecord(ev[3], s1);
        }
        gat_kernel<<<ceil_div(NC * 32, 256), 256>>>(
            off_m, src_m, xl, xr, n2c_att + l * HID, n2c_bias + l * HID,
            ln_cg + l * HID, ln_cb + l * HID, xc, NC, last ? out : nullptr);
        if (last) break;  // layer-3 c2n is dead work (output depends only on xc)

        // fork: xr(next) = xc @ n2c_wr[l+1] (needs updated xc; overlaps gat_c2n)
        cudaEventRecord(ev[4], 0);
        cudaStreamWaitEvent(s1, ev[4], 0);
        mm_gemm_p<<<GRIDP, 256, MM_SMEM, s1>>>(xc, wth + (1 * 4 + (l + 1)) * WSZ,
                                               wtl + (1 * 4 + (l + 1)) * WSZ,
                                               n2c_br + (l + 1) * HID, xr, NC);
        cudaEventRecord(ev[5], s1);

        // s0: xl2 = xc @ c2n_wl[l]
        mm_gemm_p<<<GRIDP, 256, MM_SMEM>>>(xc, wth + (2 * 4 + l) * WSZ,
                                           wtl + (2 * 4 + l) * WSZ,
                                           c2n_bl + l * HID, xl2, NC);
        cudaStreamWaitEvent(0, ev[3], 0);  // join: xr2 ready
        gat_kernel<<<ceil_div(NN * 32, 256), 256>>>(
            off_c, src_c, xl2, xr2, c2n_att + l * HID, c2n_bias + l * HID,
            ln_ng + l * HID, ln_nb + l * HID, xn, NN, nullptr);
        // s0: xl(next) = xn @ n2c_wl[l+1]
        mm_gemm_p<<<GRIDP, 256, MM_SMEM>>>(xn, wth + (0 * 4 + (l + 1)) * WSZ,
                                           wtl + (0 * 4 + (l + 1)) * WSZ,
                                           n2c_bl + (l + 1) * HID, xl, NN);
        cudaStreamWaitEvent(0, ev[5], 0);  // join: xr(next) ready
    }
}

// round 15
// speedup vs baseline: 1.1740x; 1.0309x over previous
#include <cuda_runtime.h>
#include <cuda_bf16.h>
#include <math.h>
#include <cstdint>

// ---------------- problem constants ----------------
#define NN 100000
#define NC 50000
#define EE 400000
#define ND 43
#define CD 2
#define HID 128
#define NL 4
#define SLOPE 0.2f
#define LNEPS 1e-5f

#define SCHUNK 2048
#define NB_M ((NC + SCHUNK - 1) / SCHUNK)   // 25
#define NB_C ((NN + SCHUNK - 1) / SCHUNK)   // 49
#define NB_T (NB_M + NB_C)                  // 74

// padded K stride for smem tiles (conflict-free ldmatrix rows)
#define PK 136
#define W_BYTES (128 * PK * 2)              // 34816 per W tile (hi or lo)
#define X_BYTES (64 * PK * 2)               // 17408 per X tile (hi or lo)
#define MM_SMEM (2 * W_BYTES + 2 * X_BYTES) // 104448 -> 2 blocks/SM
#define XH_OFF (2 * W_BYTES)
#define XL_OFF (2 * W_BYTES + X_BYTES)
#define WL_OFF (W_BYTES)
#define GRIDP 296                            // 2 blocks/SM x 148 SMs

// ---------------- device scratch (static, no allocation) ----------------
__device__ float g_xn[(size_t)NN * HID];
__device__ float g_xc[(size_t)NC * HID];
__device__ __nv_bfloat16 g_xl[(size_t)NN * HID];    // n2c wl output (NN rows, bf16)
__device__ __nv_bfloat16 g_xr[(size_t)NC * HID];    // n2c wr output (NC rows, bf16)
__device__ __nv_bfloat16 g_xl2[(size_t)NC * HID];   // c2n wl output (NC rows, bf16)
__device__ __nv_bfloat16 g_xr2[(size_t)NN * HID];   // c2n wr output (NN rows, bf16)
__device__ int g_deg_m[NC];
__device__ int g_cur_m[NC];
__device__ int g_deg_c[NN];
__device__ int g_cur_c[NN];
__device__ int g_off_m[NC + 1];
__device__ int g_off_c[NN + 1];
__device__ int g_src_m[EE];
__device__ int g_src_c[EE];
__device__ int g_part[128];
// transposed+split weights: 16 matrices [n][k] bf16 (idx = group*4 + layer)
__device__ __nv_bfloat16 g_wth[16 * HID * HID];
__device__ __nv_bfloat16 g_wtl[16 * HID * HID];

// ---------------- helpers ----------------
__device__ __forceinline__ void mma16816(float* d, const uint32_t* a, const uint32_t* b) {
    asm volatile(
        "mma.sync.aligned.m16n8k16.row.col.f32.bf16.bf16.f32 "
        "{%0,%1,%2,%3}, {%4,%5,%6,%7}, {%8,%9}, {%0,%1,%2,%3};"
        : "+f"(d[0]), "+f"(d[1]), "+f"(d[2]), "+f"(d[3])
        : "r"(a[0]), "r"(a[1]), "r"(a[2]), "r"(a[3]), "r"(b[0]), "r"(b[1]));
}
__device__ __forceinline__ void ldsm_x4(uint32_t* r, uint32_t addr) {
    asm volatile("ldmatrix.sync.aligned.m8n8.x4.shared.b16 {%0,%1,%2,%3}, [%4];"
                 : "=r"(r[0]), "=r"(r[1]), "=r"(r[2]), "=r"(r[3])
                 : "r"(addr));
}
__device__ __forceinline__ uint32_t smem_u32(const void* p) {
    uint32_t a;
    asm("{ .reg .u64 t; cvta.to.shared.u64 t, %1; cvt.u32.u64 %0, t; }" : "=r"(a) : "l"(p));
    return a;
}
__device__ __forceinline__ void split4(float4 x, uint2& hi, uint2& lo) {
    __nv_bfloat162 h01 = __floats2bfloat162_rn(x.x, x.y);
    __nv_bfloat162 h23 = __floats2bfloat162_rn(x.z, x.w);
    float r0 = x.x - __low2float(h01);
    float r1 = x.y - __high2float(h01);
    float r2 = x.z - __low2float(h23);
    float r3 = x.w - __high2float(h23);
    __nv_bfloat162 l01 = __floats2bfloat162_rn(r0, r1);
    __nv_bfloat162 l23 = __floats2bfloat162_rn(r2, r3);
    hi.x = *reinterpret_cast<uint32_t*>(&h01);
    hi.y = *reinterpret_cast<uint32_t*>(&h23);
    lo.x = *reinterpret_cast<uint32_t*>(&l01);
    lo.y = *reinterpret_cast<uint32_t*>(&l23);
}
// load 4 bf16 (8B) and convert to float4
__device__ __forceinline__ float4 ld_bf4(const __nv_bfloat16* p) {
    uint2 raw = *reinterpret_cast<const uint2*>(p);
    __nv_bfloat162 p01 = *reinterpret_cast<__nv_bfloat162*>(&raw.x);
    __nv_bfloat162 p23 = *reinterpret_cast<__nv_bfloat162*>(&raw.y);
    float2 f01 = __bfloat1622float2(p01);
    float2 f23 = __bfloat1622float2(p23);
    return make_float4(f01.x, f01.y, f23.x, f23.y);
}

// ---------------- weight prep: transpose + bf16 split (16 matrices) ----------------
__global__ void prep_weights_kernel(const float* __restrict__ n2c_wl,
                                    const float* __restrict__ n2c_wr,
                                    const float* __restrict__ c2n_wl,
                                    const float* __restrict__ c2n_wr,
                                    __nv_bfloat16* __restrict__ wth,
                                    __nv_bfloat16* __restrict__ wtl) {
    int idx = blockIdx.x;  // 0..15
    int grp = idx >> 2, lay = idx & 3;
    const float* W = (grp == 0) ? n2c_wl : (grp == 1) ? n2c_wr : (grp == 2) ? c2n_wl : c2n_wr;
    W += (size_t)lay * HID * HID;
    __nv_bfloat16* oh = wth + (size_t)idx * HID * HID;
    __nv_bfloat16* ol = wtl + (size_t)idx * HID * HID;
    for (int e = threadIdx.x; e < HID * HID; e += blockDim.x) {
        int k = e >> 7, n = e & 127;
        float w = W[e];  // W[k][n]
        __nv_bfloat16 h = __float2bfloat16_rn(w);
        float r = w - __bfloat162float(h);
        oh[n * HID + k] = h;
        ol[n * HID + k] = __float2bfloat16_rn(r);
    }
}

// ---------------- persistent HMMA GEMM: Y[N,128] = bf16(X[N,128] @ W + b) ------------
__global__ void __launch_bounds__(256, 2)
mm_gemm_p(const float* __restrict__ X, const __nv_bfloat16* __restrict__ Gh,
          const __nv_bfloat16* __restrict__ Gl, const float* __restrict__ bias,
          __nv_bfloat16* __restrict__ Y, int N) {
    extern __shared__ char smem[];
    __nv_bfloat16* Wh = (__nv_bfloat16*)(smem);
    __nv_bfloat16* Wl = (__nv_bfloat16*)(smem + WL_OFF);
    __nv_bfloat16* Xh = (__nv_bfloat16*)(smem + XH_OFF);
    __nv_bfloat16* Xl = (__nv_bfloat16*)(smem + XL_OFF);

    int tid = threadIdx.x;
    int lane = tid & 31;
    int wid = tid >> 5;
    uint32_t sbase = smem_u32(smem);

#pragma unroll
    for (int it = 0; it < 8; it++) {
        int n = it * 16 + (tid >> 4);
        int kc = (tid & 15) * 8;
        uint4 vh = *reinterpret_cast<const uint4*>(Gh + n * HID + kc);
        uint4 vl = *reinterpret_cast<const uint4*>(Gl + n * HID + kc);
        *reinterpret_cast<uint4*>(&Wh[n * PK + kc]) = vh;
        *reinterpret_cast<uint4*>(&Wl[n * PK + kc]) = vl;
    }

    int row0 = (wid & 1) * 32;
    int col0 = (wid >> 1) * 32;
    int gr4 = lane >> 2;
    int l2 = (lane & 3) * 2;

    uint32_t aoff = (uint32_t)(((row0 + (lane & 15)) * PK + ((lane >> 4) & 1) * 8) * 2);
    uint32_t boff = (uint32_t)(((col0 + (lane & 7) + ((lane >> 4) & 1) * 8) * PK +
                                ((lane >> 3) & 1) * 8) * 2);

    int ntiles = (N + 63) >> 6;
#pragma unroll 1
    for (int t = blockIdx.x; t < ntiles; t += gridDim.x) {
        int rb = t * 64;
        __syncthreads();
#pragma unroll
        for (int it = 0; it < 8; it++) {
            int r = it * 8 + (tid >> 5);
            int gr = rb + r;
            int kc = (tid & 31) * 4;
            float4 x = (gr < N) ? *reinterpret_cast<const float4*>(X + (size_t)gr * HID + kc)
                                : make_float4(0.f, 0.f, 0.f, 0.f);
            uint2 hi, lo;
            split4(x, hi, lo);
            *reinterpret_cast<uint2*>(&Xh[r * PK + kc]) = hi;
            *reinterpret_cast<uint2*>(&Xl[r * PK + kc]) = lo;
        }
        __syncthreads();

        float acc[2][4][4];
#pragma unroll
        for (int mt = 0; mt < 2; mt++)
#pragma unroll
            for (int nt = 0; nt < 4; nt++)
#pragma unroll
                for (int j = 0; j < 4; j++) acc[mt][nt][j] = 0.f;

#pragma unroll
        for (int ks = 0; ks < 8; ks++) {
            uint32_t kb = ks * 32;
            uint32_t ah[2][4], al[2][4], bh[4][2], bl[4][2];
            uint32_t aXh = sbase + XH_OFF + aoff + kb;
            uint32_t aXl = sbase + XL_OFF + aoff + kb;
            ldsm_x4(ah[0], aXh);
            ldsm_x4(ah[1], aXh + 16 * PK * 2);
            ldsm_x4(al[0], aXl);
            ldsm_x4(al[1], aXl + 16 * PK * 2);
            uint32_t bWh = sbase + boff + kb;
            uint32_t bWl = sbase + WL_OFF + boff + kb;
            ldsm_x4(&bh[0][0], bWh);
            ldsm_x4(&bh[2][0], bWh + 16 * PK * 2);
            ldsm_x4(&bl[0][0], bWl);
            ldsm_x4(&bl[2][0], bWl + 16 * PK * 2);
#pragma unroll
            for (int mt = 0; mt < 2; mt++)
#pragma unroll
                for (int nt = 0; nt < 4; nt++) {
                    mma16816(acc[mt][nt], ah[mt], bh[nt]);
                    mma16816(acc[mt][nt], ah[mt], bl[nt]);
                    mma16816(acc[mt][nt], al[mt], bh[nt]);
                }
        }

#pragma unroll
        for (int nt = 0; nt < 4; nt++) {
            int c = col0 + nt * 8 + l2;
            float bx = bias[c], by = bias[c + 1];
#pragma unroll
            for (int mt = 0; mt < 2; mt++) {
                int r0 = rb + row0 + mt * 16 + gr4;
                if (r0 < N) {
                    __nv_bfloat162 v = __floats2bfloat162_rn(acc[mt][nt][0] + bx,
                                                             acc[mt][nt][1] + by);
                    *reinterpret_cast<__nv_bfloat162*>(Y + (size_t)r0 * HID + c) = v;
                }
                if (r0 + 8 < N) {
                    __nv_bfloat162 v = __floats2bfloat162_rn(acc[mt][nt][2] + bx,
                                                             acc[mt][nt][3] + by);
                    *reinterpret_cast<__nv_bfloat162*>(Y + (size_t)(r0 + 8) * HID + c) = v;
                }
            }
        }
    }
}

// ---------------- merged input projection ----------------
__global__ void proj_both_kernel(const float* __restrict__ Xn, const float* __restrict__ Wn,
                                 const float* __restrict__ bn, float* __restrict__ Yn,
                                 const float* __restrict__ Xc, const float* __restrict__ Wc,
                                 const float* __restrict__ bc, float* __restrict__ Yc) {
    __shared__ float xs[64];
    int blk = blockIdx.x;
    int n = threadIdx.x;  // 128 threads
    const float* X;
    const float* W;
    const float* b;
    float* Y;
    int row, K;
    if (blk < NN) {
        X = Xn; W = Wn; b = bn; Y = Yn; row = blk; K = ND;
    } else {
        X = Xc; W = Wc; b = bc; Y = Yc; row = blk - NN; K = CD;
    }
    if (n < K) xs[n] = X[(size_t)row * K + n];
    __syncthreads();
    float acc = b[n];
    for (int k = 0; k < K; k++) acc = fmaf(xs[k], W[k * HID + n], acc);
    Y[(size_t)row * HID + n] = acc;
}

// ---------------- CSR build ----------------
__global__ void build_zero_kernel(int* __restrict__ dm, int* __restrict__ dc) {
    int i = blockIdx.x * blockDim.x + threadIdx.x;
    if (i < NC) dm[i] = 0;
    if (i < NN) dc[i] = 0;
}
__global__ void build_hist_kernel(const int* __restrict__ mdst, const int* __restrict__ cdst,
                                  int* __restrict__ dm, int* __restrict__ dc, int E) {
    int i = blockIdx.x * blockDim.x + threadIdx.x;
    if (i < E)
        atomicAdd(&dm[mdst[i]], 1);
    else if (i < 2 * E)
        atomicAdd(&dc[cdst[i - E]], 1);
}
__global__ void scanA_kernel(const int* __restrict__ dm, const int* __restrict__ dc,
                             int* __restrict__ part) {
    int b = blockIdx.x;
    const int* deg;
    int n, c0;
    if (b < NB_M) { deg = dm; n = NC; c0 = b * SCHUNK; }
    else          { deg = dc; n = NN; c0 = (b - NB_M) * SCHUNK; }
    int t = threadIdx.x;
    int base = c0 + t * 8;
    int s = 0;
#pragma unroll
    for (int i = 0; i < 8; i++) {
        int idx = base + i;
        if (idx < n) s += deg[idx];
    }
#pragma unroll
    for (int o = 16; o > 0; o >>= 1) s += __shfl_xor_sync(0xffffffffu, s, o);
    __shared__ int red[8];
    if ((t & 31) == 0) red[t >> 5] = s;
    __syncthreads();
    if (t == 0) {
        int tot = 0;
#pragma unroll
        for (int i = 0; i < 8; i++) tot += red[i];
        part[b] = tot;
    }
}
__global__ void scanB_kernel(int* __restrict__ part, int* __restrict__ om,
                             int* __restrict__ oc, int E) {
    __shared__ int sm_[128];
    int t = threadIdx.x;  // 128
    sm_[t] = (t < NB_T) ? part[t] : 0;
    __syncthreads();
    if (t == 0) {
        int run = 0;
        for (int i = 0; i < NB_M; i++) { int x = sm_[i]; sm_[i] = run; run += x; }
        run = 0;
        for (int i = NB_M; i < NB_T; i++) { int x = sm_[i]; sm_[i] = run; run += x; }
        om[NC] = E;
        oc[NN] = E;
    }
    __syncthreads();
    if (t < NB_T) part[t] = sm_[t];
}
__global__ void scanC_kernel(const int* __restrict__ dm, const int* __restrict__ dc,
                             const int* __restrict__ part, int* __restrict__ om,
                             int* __restrict__ oc, int* __restrict__ cm,
                             int* __restrict__ cc) {
    int b = blockIdx.x;
    const int* deg;
    int *off, *cur;
    int n, c0;
    if (b < NB_M) { deg = dm; off = om; cur = cm; n = NC; c0 = b * SCHUNK; }
    else          { deg = dc; off = oc; cur = cc; n = NN; c0 = (b - NB_M) * SCHUNK; }
    int t = threadIdx.x;  // 256
    int base = c0 + t * 8;
    int v[8];
    int s = 0;
#pragma unroll
    for (int i = 0; i < 8; i++) {
        int idx = base + i;
        v[i] = (idx < n) ? deg[idx] : 0;
        s += v[i];
    }
    int lane = t & 31, w = t >> 5;
    int pre = s;
#pragma unroll
    for (int o = 1; o < 32; o <<= 1) {
        int u = __shfl_up_sync(0xffffffffu, pre, o);
        if (lane >= o) pre += u;
    }
    __shared__ int wsum[8];
    if (lane == 31) wsum[w] = pre;
    __syncthreads();
    if (t == 0) {
        int run = 0;
#pragma unroll
        for (int i = 0; i < 8; i++) { int x = wsum[i]; wsum[i] = run; run += x; }
    }
    __syncthreads();
    int ex = pre - s + wsum[w] + part[b];
#pragma unroll
    for (int i = 0; i < 8; i++) {
        int idx = base + i;
        if (idx < n) {
            off[idx] = ex;
            cur[idx] = ex;
            ex += v[i];
        }
    }
}
__global__ void build_scatter_kernel(const int* __restrict__ msrc, const int* __restrict__ mdst,
                                     const int* __restrict__ csrc_e, const int* __restrict__ cdst,
                                     int* __restrict__ cm, int* __restrict__ cc,
                                     int* __restrict__ sm, int* __restrict__ sc, int E) {
    int i = blockIdx.x * blockDim.x + threadIdx.x;
    if (i < E) {
        int p = atomicAdd(&cm[mdst[i]], 1);
        sm[p] = msrc[i];
    } else if (i < 2 * E) {
        int j = i - E;
        int p = atomicAdd(&cc[cdst[j]], 1);
        sc[p] = csrc_e[j];
    }
}

// ---------------- fused GATv2: lane-prefetched 4-edge online softmax + LN ------------
__device__ __forceinline__ float edge_score(float4 xl4, float4 xr4, float4 at4) {
    float vx = xl4.x + xr4.x; vx = vx > 0.f ? vx : SLOPE * vx;
    float vy = xl4.y + xr4.y; vy = vy > 0.f ? vy : SLOPE * vy;
    float vz = xl4.z + xr4.z; vz = vz > 0.f ? vz : SLOPE * vz;
    float vw = xl4.w + xr4.w; vw = vw > 0.f ? vw : SLOPE * vw;
    float sc = vx * at4.x + vy * at4.y + vz * at4.z + vw * at4.w;
    sc += __shfl_xor_sync(0xffffffffu, sc, 1);
    sc += __shfl_xor_sync(0xffffffffu, sc, 2);
    sc += __shfl_xor_sync(0xffffffffu, sc, 4);
    return sc;
}

// xl/xr are bf16 feature rows. mean_out == nullptr: write LN result to x.
// Otherwise: skip x store, block-reduce into mean_out (scaled 1/n_dst).
// NOTE: grids are exact (n_dst*32 divisible by 256) -> no early-exit warps.
__global__ void gat_kernel(const int* __restrict__ off, const int* __restrict__ csrc,
                           const __nv_bfloat16* __restrict__ xl,
                           const __nv_bfloat16* __restrict__ xr,
                           const float* __restrict__ att, const float* __restrict__ bias,
                           const float* __restrict__ lng, const float* __restrict__ lnb,
                           float* __restrict__ x, int n_dst, float* __restrict__ mean_out) {
    __shared__ float blk[128];
    int d = (blockIdx.x * blockDim.x + threadIdx.x) >> 5;
    if (d >= n_dst) return;
    int l = threadIdx.x & 31;
    int ofs = l * 4;

    int e0 = off[d], e1 = off[d + 1];
    // independent loads issued up-front (max MLP before the edge chain)
    float4 xr4 = ld_bf4(xr + (size_t)d * HID + ofs);
    float4 at4 = *(const float4*)(att + ofs);
    float4 x4 = *(const float4*)(x + (size_t)d * HID + ofs);
    float4 b4 = *(const float4*)(bias + ofs);

    float m = -1e30f, den = 0.f;
    float4 acc = make_float4(0.f, 0.f, 0.f, 0.f);

    // windows of 32 edges: ONE coalesced index load per window, shfl-distributed
    for (int w = e0; w < e1; w += 32) {
        int nw = e1 - w;
        if (nw > 32) nw = 32;
        int widx = (w + l < e1) ? csrc[w + l] : 0;
        for (int c = 0; c < nw; c += 4) {
            int ns = nw - c;
            int s0 = __shfl_sync(0xffffffffu, widx, c);
            int s1 = __shfl_sync(0xffffffffu, widx, (ns > 1) ? c + 1 : c);
            int s2 = __shfl_sync(0xffffffffu, widx, (ns > 2) ? c + 2 : c);
            int s3 = __shfl_sync(0xffffffffu, widx, (ns > 3) ? c + 3 : c);
            float4 v0 = ld_bf4(xl + (size_t)s0 * HID + ofs);
            float4 v1 = ld_bf4(xl + (size_t)s1 * HID + ofs);
            float4 v2 = ld_bf4(xl + (size_t)s2 * HID + ofs);
            float4 v3 = ld_bf4(xl + (size_t)s3 * HID + ofs);
            float sc0 = edge_score(v0, xr4, at4);
            float sc1 = edge_score(v1, xr4, at4);
            float sc2 = edge_score(v2, xr4, at4);
            float sc3 = edge_score(v3, xr4, at4);
            if (ns < 4) sc3 = -1e30f;
            if (ns < 3) sc2 = -1e30f;
            if (ns < 2) sc1 = -1e30f;
            float gm = fmaxf(fmaxf(sc0, sc1), fmaxf(sc2, sc3));
            float nm = fmaxf(m, gm);
            float f = __expf(m - nm);
            float e0x = __expf(sc0 - nm);
            float e1x = __expf(sc1 - nm);
            float e2x = __expf(sc2 - nm);
            float e3x = __expf(sc3 - nm);
            den = den * f + ((e0x + e1x) + (e2x + e3x));
            acc.x = acc.x * f + (fmaf(e0x, v0.x, e1x * v1.x) + fmaf(e2x, v2.x, e3x * v3.x));
            acc.y = acc.y * f + (fmaf(e0x, v0.y, e1x * v1.y) + fmaf(e2x, v2.y, e3x * v3.y));
            acc.z = acc.z * f + (fmaf(e0x, v0.z, e1x * v1.z) + fmaf(e2x, v2.z, e3x * v3.z));
            acc.w = acc.w * f + (fmaf(e0x, v0.w, e1x * v1.w) + fmaf(e2x, v2.w, e3x * v3.w));
            m = nm;
        }
    }

    float inv = (e1 > e0) ? 1.0f / den : 0.0f;
    float4 o;
    o.x = acc.x * inv + b4.x + x4.x;
    o.y = acc.y * inv + b4.y + x4.y;
    o.z = acc.z * inv + b4.z + x4.z;
    o.w = acc.w * inv + b4.w + x4.w;

    float s = o.x + o.y + o.z + o.w;
#pragma unroll
    for (int k = 16; k > 0; k >>= 1) s += __shfl_xor_sync(0xffffffffu, s, k);
    float mu = s * (1.0f / HID);
    float q = (o.x - mu) * (o.x - mu) + (o.y - mu) * (o.y - mu) +
              (o.z - mu) * (o.z - mu) + (o.w - mu) * (o.w - mu);
#pragma unroll
    for (int k = 16; k > 0; k >>= 1) q += __shfl_xor_sync(0xffffffffu, q, k);
    float rs = rsqrtf(q * (1.0f / HID) + LNEPS);
    float4 g4 = *(const float4*)(lng + ofs);
    float4 bb4 = *(const float4*)(lnb + ofs);
    o.x = (o.x - mu) * rs * g4.x + bb4.x;
    o.y = (o.y - mu) * rs * g4.y + bb4.y;
    o.z = (o.z - mu) * rs * g4.z + bb4.z;
    o.w = (o.w - mu) * rs * g4.w + bb4.w;

    if (mean_out == nullptr) {
        *(float4*)(x + (size_t)d * HID + ofs) = o;
    } else {
        if (threadIdx.x < 128) blk[threadIdx.x] = 0.f;
        __syncthreads();
        atomicAdd(&blk[ofs + 0], o.x);
        atomicAdd(&blk[ofs + 1], o.y);
        atomicAdd(&blk[ofs + 2], o.z);
        atomicAdd(&blk[ofs + 3], o.w);
        __syncthreads();
        if (threadIdx.x < 128)
            atomicAdd(&mean_out[threadIdx.x], blk[threadIdx.x] * (1.0f / n_dst));
    }
}

// ---------------- output zero ----------------
__global__ void zero_out_kernel(float* __restrict__ out) { out[threadIdx.x] = 0.0f; }

// ---------------- host orchestration ----------------
static inline int ceil_div(int a, int b) { return (a + b - 1) / b; }

extern "C" void kernel_launch(void* const* d_in, const int* in_sizes, int n_in,
                              void* d_out, int out_size) {
    const float* x_node       = (const float*)d_in[0];
    const float* x_class      = (const float*)d_in[1];
    const int*   member_src   = (const int*)d_in[2];
    const int*   member_dst   = (const int*)d_in[3];
    const int*   contains_src = (const int*)d_in[4];
    const int*   contains_dst = (const int*)d_in[5];
    const float* npw = (const float*)d_in[6];
    const float* npb = (const float*)d_in[7];
    const float* cpw = (const float*)d_in[8];
    const float* cpb = (const float*)d_in[9];
    const float* n2c_wl   = (const float*)d_in[10];
    const float* n2c_bl   = (const float*)d_in[11];
    const float* n2c_wr   = (const float*)d_in[12];
    const float* n2c_br   = (const float*)d_in[13];
    const float* n2c_att  = (const float*)d_in[14];
    const float* n2c_bias = (const float*)d_in[15];
    const float* c2n_wl   = (const float*)d_in[16];
    const float* c2n_bl   = (const float*)d_in[17];
    const float* c2n_wr   = (const float*)d_in[18];
    const float* c2n_br   = (const float*)d_in[19];
    const float* c2n_att  = (const float*)d_in[20];
    const float* c2n_bias = (const float*)d_in[21];
    const float* ln_cg = (const float*)d_in[22];
    const float* ln_cb = (const float*)d_in[23];
    const float* ln_ng = (const float*)d_in[24];
    const float* ln_nb = (const float*)d_in[25];
    float* out = (float*)d_out;

    int E = in_sizes[2];

    float *xn, *xc;
    __nv_bfloat16 *xl, *xr, *xl2, *xr2, *wth, *wtl;
    int *deg_m, *cur_m, *deg_c, *cur_c, *off_m, *off_c, *src_m, *src_c, *part;
    cudaGetSymbolAddress((void**)&xn, g_xn);
    cudaGetSymbolAddress((void**)&xc, g_xc);
    cudaGetSymbolAddress((void**)&xl, g_xl);
    cudaGetSymbolAddress((void**)&xr, g_xr);
    cudaGetSymbolAddress((void**)&xl2, g_xl2);
    cudaGetSymbolAddress((void**)&xr2, g_xr2);
    cudaGetSymbolAddress((void**)&deg_m, g_deg_m);
    cudaGetSymbolAddress((void**)&cur_m, g_cur_m);
    cudaGetSymbolAddress((void**)&deg_c, g_deg_c);
    cudaGetSymbolAddress((void**)&cur_c, g_cur_c);
    cudaGetSymbolAddress((void**)&off_m, g_off_m);
    cudaGetSymbolAddress((void**)&off_c, g_off_c);
    cudaGetSymbolAddress((void**)&src_m, g_src_m);
    cudaGetSymbolAddress((void**)&src_c, g_src_c);
    cudaGetSymbolAddress((void**)&part, g_part);
    cudaGetSymbolAddress((void**)&wth, g_wth);
    cudaGetSymbolAddress((void**)&wtl, g_wtl);

    cudaFuncSetAttribute(mm_gemm_p, cudaFuncAttributeMaxDynamicSharedMemorySize, MM_SMEM);

    // side streams + fork/join events (created once; host-side only)
    static cudaStream_t s1 = nullptr, s2 = nullptr;
    static cudaEvent_t ev[8];
    if (s1 == nullptr) {
        cudaStreamCreateWithFlags(&s1, cudaStreamNonBlocking);
        cudaStreamCreateWithFlags(&s2, cudaStreamNonBlocking);
        for (int i = 0; i < 8; i++) cudaEventCreateWithFlags(&ev[i], cudaEventDisableTiming);
    }

    int g2E = ceil_div(2 * E, 256);
    const size_t WSZ = (size_t)HID * HID;

    // fork CSR build onto s2 immediately (depends only on edge lists)
    cudaEventRecord(ev[6], 0);
    cudaStreamWaitEvent(s2, ev[6], 0);
    build_zero_kernel<<<ceil_div(NN, 256), 256, 0, s2>>>(deg_m, deg_c);
    build_hist_kernel<<<g2E, 256, 0, s2>>>(member_dst, contains_dst, deg_m, deg_c, E);
    scanA_kernel<<<NB_T, 256, 0, s2>>>(deg_m, deg_c, part);
    scanB_kernel<<<1, 128, 0, s2>>>(part, off_m, off_c, E);
    scanC_kernel<<<NB_T, 256, 0, s2>>>(deg_m, deg_c, part, off_m, off_c, cur_m, cur_c);
    build_scatter_kernel<<<g2E, 256, 0, s2>>>(member_src, member_dst, contains_src,
                                              contains_dst, cur_m, cur_c, src_m, src_c, E);
    cudaEventRecord(ev[7], s2);  // CSR done

    // s0: weight prep + input projections
    prep_weights_kernel<<<16, 256>>>(n2c_wl, n2c_wr, c2n_wl, c2n_wr, wth, wtl);
    proj_both_kernel<<<NN + NC, 128>>>(x_node, npw, npb, xn, x_class, cpw, cpb, xc);
    zero_out_kernel<<<1, 128>>>(out);

    // fork: xr = xc @ n2c_wr[0] on s1; xl = xn @ n2c_wl[0] on s0
    cudaEventRecord(ev[0], 0);
    cudaStreamWaitEvent(s1, ev[0], 0);
    mm_gemm_p<<<GRIDP, 256, MM_SMEM, s1>>>(xc, wth + (1 * 4 + 0) * WSZ,
                                           wtl + (1 * 4 + 0) * WSZ, n2c_br, xr, NC);
    cudaEventRecord(ev[1], s1);
    mm_gemm_p<<<GRIDP, 256, MM_SMEM>>>(xn, wth + (0 * 4 + 0) * WSZ,
                                       wtl + (0 * 4 + 0) * WSZ, n2c_bl, xl, NN);
    cudaStreamWaitEvent(0, ev[1], 0);  // join: xr ready
    cudaStreamWaitEvent(0, ev[7], 0);  // join: CSR ready

    for (int l = 0; l < NL; l++) {
        bool last = (l == NL - 1);
        if (!last) {
            // fork: xr2 = xn @ c2n_wr[l] (independent of gat_n2c)
            cudaEventRecord(ev[2], 0);
            cudaStreamWaitEvent(s1, ev[2], 0);
            mm_gemm_p<<<GRIDP, 256, MM_SMEM, s1>>>(xn, wth + (3 * 4 + l) * WSZ,
                                                   wtl + (3 * 4 + l) * WSZ,
                                                   c2n_br + l * HID, xr2, NN);
            cudaEventRecord(ev[3], s1);
        }
        gat_kernel<<<ceil_div(NC * 32, 256), 256>>>(
            off_m, src_m, xl, xr, n2c_att + l * HID, n2c_bias + l * HID,
            ln_cg + l * HID, ln_cb + l * HID, xc, NC, last ? out : nullptr);
        if (last) break;  // layer-3 c2n is dead work (output depends only on xc)

        // fork: xr(next) = xc @ n2c_wr[l+1] (needs updated xc; overlaps gat_c2n)
        cudaEventRecord(ev[4], 0);
        cudaStreamWaitEvent(s1, ev[4], 0);
        mm_gemm_p<<<GRIDP, 256, MM_SMEM, s1>>>(xc, wth + (1 * 4 + (l + 1)) * WSZ,
                                               wtl + (1 * 4 + (l + 1)) * WSZ,
                                               n2c_br + (l + 1) * HID, xr, NC);
        cudaEventRecord(ev[5], s1);

        // s0: xl2 = xc @ c2n_wl[l]
        mm_gemm_p<<<GRIDP, 256, MM_SMEM>>>(xc, wth + (2 * 4 + l) * WSZ,
                                           wtl + (2 * 4 + l) * WSZ,
                                           c2n_bl + l * HID, xl2, NC);
        cudaStreamWaitEvent(0, ev[3], 0);  // join: xr2 ready
        gat_kernel<<<ceil_div(NN * 32, 256), 256>>>(
            off_c, src_c, xl2, xr2, c2n_att + l * HID, c2n_bias + l * HID,
            ln_ng + l * HID, ln_nb + l * HID, xn, NN, nullptr);
        // s0: xl(next) = xn @ n2c_wl[l+1]
        mm_gemm_p<<<GRIDP, 256, MM_SMEM>>>(xn, wth + (0 * 4 + (l + 1)) * WSZ,
                                           wtl + (0 * 4 + (l + 1)) * WSZ,
                                           n2c_bl + (l + 1) * HID, xl, NN);
        cudaStreamWaitEvent(0, ev[5], 0);  // join: xr(next) ready
    }
}